// round 14
// baseline (speedup 1.0000x reference)
#include <cuda_runtime.h>
#include <cuda_bf16.h>
#include <cstdint>

#define BATCH  4
#define CH     256
#define IMG    256
#define WSZ    8
#define NT     64
#define NHEAD  8
#define GN_EPS 1e-5f
#define NTOK   (BATCH * IMG * IMG)          // 262144

// ---- device-global scratch (allocation is banned) ----
__device__ float    g_mean[BATCH * 32];
__device__ float    g_rstd[BATCH * 32];
__device__ uint32_t g_xh[(size_t)NTOK * 128];   // GN(x) bf16x2 hi, [token][128]
__device__ uint32_t g_xl[(size_t)NTOK * 128];   // lo residual
__device__ uint32_t g_wh[1024 * 128];           // Wq|Wk|Wv|Wo rows, bf16x2 hi
__device__ uint32_t g_wl[1024 * 128];
__device__ uint32_t g_qkh[(size_t)NTOK * 256];  // [token][Q 128 pairs | K 128 pairs] hi
__device__ uint32_t g_qkl[(size_t)NTOK * 256];
__device__ float    g_v  [(size_t)NTOK * 256];  // V, tf32-rounded fp32
__device__ uint32_t g_ath[(size_t)NTOK * 128];  // attention out, split bf16
__device__ uint32_t g_atl[(size_t)NTOK * 128];

// ---------------------------------------------------------------------------
// helpers
// ---------------------------------------------------------------------------
__device__ __forceinline__ uint32_t f2tf(float f) {
    uint32_t u; asm("cvt.rna.tf32.f32 %0, %1;" : "=r"(u) : "f"(f)); return u;
}
__device__ __forceinline__ void mma_tf32(float d[4],
    uint32_t a0, uint32_t a1, uint32_t a2, uint32_t a3,
    uint32_t b0, uint32_t b1)
{
    asm("mma.sync.aligned.m16n8k8.row.col.f32.tf32.tf32.f32 "
        "{%0,%1,%2,%3},{%4,%5,%6,%7},{%8,%9},{%0,%1,%2,%3};"
        : "+f"(d[0]), "+f"(d[1]), "+f"(d[2]), "+f"(d[3])
        : "r"(a0), "r"(a1), "r"(a2), "r"(a3), "r"(b0), "r"(b1));
}
__device__ __forceinline__ void mma_bf16(float d[4], uint4 a, uint32_t b0, uint32_t b1)
{
    asm("mma.sync.aligned.m16n8k16.row.col.f32.bf16.bf16.f32 "
        "{%0,%1,%2,%3},{%4,%5,%6,%7},{%8,%9},{%0,%1,%2,%3};"
        : "+f"(d[0]), "+f"(d[1]), "+f"(d[2]), "+f"(d[3])
        : "r"(a.x), "r"(a.y), "r"(a.z), "r"(a.w), "r"(b0), "r"(b1));
}
__device__ __forceinline__ void ldmx4(uint4& d, uint32_t addr) {
    asm volatile("ldmatrix.sync.aligned.m8n8.x4.shared.b16 {%0,%1,%2,%3}, [%4];"
        : "=r"(d.x), "=r"(d.y), "=r"(d.z), "=r"(d.w) : "r"(addr));
}
__device__ __forceinline__ uint32_t s2u(const void* p) {
    uint32_t a;
    asm("{ .reg .u64 t; cvta.to.shared.u64 t, %1; cvt.u32.u64 %0, t; }" : "=r"(a) : "l"(p));
    return a;
}
__device__ __forceinline__ void cpa16(uint32_t saddr, const void* gptr) {
    asm volatile("cp.async.cg.shared.global [%0], [%1], 16;" :: "r"(saddr), "l"(gptr));
}
__device__ __forceinline__ void tok2pix(int m, int& b, int& pix) {
    b = m >> 16;
    const int win = (m >> 6) & 1023;
    const int t   = m & 63;
    pix = ((win >> 5) * WSZ + (t >> 3)) * IMG + (win & 31) * WSZ + (t & 7);
}
__device__ __forceinline__ uint32_t bfsplit2(float a, float b, uint32_t& lo) {
    __nv_bfloat16 ah = __float2bfloat16(a);
    __nv_bfloat16 bh = __float2bfloat16(b);
    __nv_bfloat16 al = __float2bfloat16(a - __bfloat162float(ah));
    __nv_bfloat16 bl = __float2bfloat16(b - __bfloat162float(bh));
    lo = (uint32_t)__bfloat16_as_ushort(al) | ((uint32_t)__bfloat16_as_ushort(bl) << 16);
    return (uint32_t)__bfloat16_as_ushort(ah) | ((uint32_t)__bfloat16_as_ushort(bh) << 16);
}

// ---------------------------------------------------------------------------
// K1: GroupNorm statistics
// ---------------------------------------------------------------------------
__global__ void gn_stats_kernel(const float* __restrict__ x)
{
    const int bg = blockIdx.x;
    const float4* p = reinterpret_cast<const float4*>(x + (size_t)bg * 8 * IMG * IMG);
    const int n4 = (8 * IMG * IMG) / 4;

    float s = 0.f, sq = 0.f;
    for (int i = threadIdx.x; i < n4; i += blockDim.x) {
        float4 v = p[i];
        s  += v.x + v.y + v.z + v.w;
        sq += v.x * v.x + v.y * v.y + v.z * v.z + v.w * v.w;
    }
    for (int o = 16; o; o >>= 1) {
        s  += __shfl_down_sync(0xFFFFFFFFu, s,  o);
        sq += __shfl_down_sync(0xFFFFFFFFu, sq, o);
    }
    __shared__ float ss[32], ssq[32];
    const int w = threadIdx.x >> 5, l = threadIdx.x & 31;
    if (l == 0) { ss[w] = s; ssq[w] = sq; }
    __syncthreads();
    if (w == 0) {
        const int nw = blockDim.x >> 5;
        s  = (l < nw) ? ss[l]  : 0.f;
        sq = (l < nw) ? ssq[l] : 0.f;
        for (int o = 16; o; o >>= 1) {
            s  += __shfl_down_sync(0xFFFFFFFFu, s,  o);
            sq += __shfl_down_sync(0xFFFFFFFFu, sq, o);
        }
        if (l == 0) {
            const float invN = 1.f / (float)(8 * IMG * IMG);
            const float m   = s * invN;
            const float var = sq * invN - m * m;
            g_mean[bg] = m;
            g_rstd[bg] = rsqrtf(var + GN_EPS);
        }
    }
}

// ---------------------------------------------------------------------------
// K0a: split all weights once (Wq|Wk|Wv|Wo -> rows 0..1023)
// ---------------------------------------------------------------------------
__global__ void prep_w_kernel(const float* __restrict__ Wq, const float* __restrict__ Wk,
                              const float* __restrict__ Wv, const float* __restrict__ Wo)
{
    const int idx = blockIdx.x * 256 + threadIdx.x;     // 0..131071
    const int r = idx >> 7, p = idx & 127;
    const float* W = (r < 256) ? Wq : ((r < 512) ? Wk : ((r < 768) ? Wv : Wo));
    const float2 w = *reinterpret_cast<const float2*>(&W[(size_t)(r & 255) * 256 + 2 * p]);
    uint32_t lo; const uint32_t hi = bfsplit2(w.x, w.y, lo);
    g_wh[idx] = hi; g_wl[idx] = lo;
}

// ---------------------------------------------------------------------------
// K0b: GN + bf16 split of x, once, token-major. 128 tokens per block.
// ---------------------------------------------------------------------------
__global__ void prep_x_kernel(const float* __restrict__ x,
                              const float* __restrict__ gnw, const float* __restrict__ gnb)
{
    __shared__ uint32_t Sh[128][17], Sl[128][17];
    const int tid = threadIdx.x;
    const int m0 = blockIdx.x * 128;

    for (int slab = 0; slab < 8; slab++) {
        __syncthreads();
        for (int i = tid; i < 2048; i += 256) {
            const int tok = i & 127, p = i >> 7;        // p 0..15
            const int c = slab * 32 + 2 * p;
            int bb, pix; tok2pix(m0 + tok, bb, pix);
            const size_t base = (size_t)bb * CH * IMG * IMG + pix;
            const float v0 = x[base + (size_t)c * (IMG * IMG)];
            const float v1 = x[base + (size_t)(c + 1) * (IMG * IMG)];
            const float mn = g_mean[bb * 32 + (c >> 3)];
            const float rs = g_rstd[bb * 32 + (c >> 3)];
            const float a = (v0 - mn) * rs * gnw[c]     + gnb[c];
            const float d = (v1 - mn) * rs * gnw[c + 1] + gnb[c + 1];
            uint32_t lo; const uint32_t hi = bfsplit2(a, d, lo);
            Sh[tok][p] = hi; Sl[tok][p] = lo;
        }
        __syncthreads();
        for (int i = tid; i < 2048; i += 256) {
            const int tok = i >> 4, p = i & 15;
            g_xh[(size_t)(m0 + tok) * 128 + slab * 16 + p] = Sh[tok][p];
            g_xl[(size_t)(m0 + tok) * 128 + slab * 16 + p] = Sl[tok][p];
        }
    }
}

// ---------------------------------------------------------------------------
// Shared GEMM mainloop: C[128,128] += A[128,256]*B[128,256]^T, 3-term bf16.
// True 2-stage double buffer: K-chunk 32, SEPARATE stage buffers (40KB each),
// 80B row stride (4 granules used) -> ldmatrix conflict-free without swizzle.
// 80KB smem, 2 CTAs/SM, warp tile 32m x 64n.
// ---------------------------------------------------------------------------
#define ST_A_H 0
#define ST_A_L 10240
#define ST_B_H 20480
#define ST_B_L 30720
#define STAGE_BYTES 40960
#define GM_SMEM (2 * STAGE_BYTES)    // 81920

__device__ __forceinline__ void fill_chunk(
    uint32_t sbase, int kc,
    const uint32_t* __restrict__ Ah_g, const uint32_t* __restrict__ Al_g,
    const uint32_t* __restrict__ Bh_g, const uint32_t* __restrict__ Bl_g)
{
    const int tid = threadIdx.x;
    const uint32_t sb = sbase + (uint32_t)(kc & 1) * STAGE_BYTES;
    #pragma unroll
    for (int i = tid; i < 512; i += 256) {
        const int r = i >> 2, j = i & 3;                      // row, granule
        const size_t gs = (size_t)r * 128 + kc * 16 + j * 4;  // uint32 index
        const uint32_t so = r * 80 + j * 16;
        cpa16(sb + ST_A_H + so, Ah_g + gs);
        cpa16(sb + ST_A_L + so, Al_g + gs);
        cpa16(sb + ST_B_H + so, Bh_g + gs);
        cpa16(sb + ST_B_L + so, Bl_g + gs);
    }
    asm volatile("cp.async.commit_group;");
}

__device__ __forceinline__ void gemm_mainloop128(
    uint32_t sbase,
    const uint32_t* __restrict__ Ah_g, const uint32_t* __restrict__ Al_g,
    const uint32_t* __restrict__ Bh_g, const uint32_t* __restrict__ Bl_g,
    float acc[2][8][4])
{
    const int tid = threadIdx.x, wid = tid >> 5, lane = tid & 31;
    const int wm = (wid & 3) * 32, wn = (wid >> 2) * 64;
    const int lrow = lane & 7, seg = lane >> 3;
    const int arow = wm + (seg & 1) * 8 + lrow;          // + mi*16
    const int brow = wn + (seg >> 1) * 8 + lrow;         // + half*32 + jj*16
    const int agc = seg >> 1;                            // + 2ks
    const int bgc = seg & 1;

    fill_chunk(sbase, 0, Ah_g, Al_g, Bh_g, Bl_g);

    for (int kc = 0; kc < 8; kc++) {
        if (kc < 7) {
            fill_chunk(sbase, kc + 1, Ah_g, Al_g, Bh_g, Bl_g);
            asm volatile("cp.async.wait_group 1;" ::: "memory");
        } else {
            asm volatile("cp.async.wait_group 0;" ::: "memory");
        }
        __syncthreads();                                  // chunk kc data visible

        const uint32_t sb = sbase + (uint32_t)(kc & 1) * STAGE_BYTES;
        #pragma unroll
        for (int ks = 0; ks < 2; ks++) {
            const int gA = 2 * ks + agc;
            const int gB = 2 * ks + bgc;
            uint4 ah[2], al[2];
            #pragma unroll
            for (int mi = 0; mi < 2; mi++) {
                const int r = arow + mi * 16;
                const uint32_t ad = sb + ST_A_H + r * 80 + gA * 16;
                ldmx4(ah[mi], ad);
                ldmx4(al[mi], ad + (ST_A_L - ST_A_H));
            }
            #pragma unroll
            for (int half = 0; half < 2; half++) {
                uint4 bh[2], bl[2];
                #pragma unroll
                for (int jj = 0; jj < 2; jj++) {
                    const int r = brow + half * 32 + jj * 16;
                    const uint32_t bd = sb + ST_B_H + r * 80 + gB * 16;
                    ldmx4(bh[jj], bd);
                    ldmx4(bl[jj], bd + (ST_B_L - ST_B_H));
                }
                #pragma unroll
                for (int jj = 0; jj < 2; jj++) {
                    const int n0 = half * 4 + 2 * jj;
                    #pragma unroll
                    for (int mi = 0; mi < 2; mi++) {
                        mma_bf16(acc[mi][n0],     ah[mi], bh[jj].x, bh[jj].y);
                        mma_bf16(acc[mi][n0],     al[mi], bh[jj].x, bh[jj].y);
                        mma_bf16(acc[mi][n0],     ah[mi], bl[jj].x, bl[jj].y);
                        mma_bf16(acc[mi][n0 + 1], ah[mi], bh[jj].z, bh[jj].w);
                        mma_bf16(acc[mi][n0 + 1], al[mi], bh[jj].z, bh[jj].w);
                        mma_bf16(acc[mi][n0 + 1], ah[mi], bl[jj].z, bl[jj].w);
                    }
                }
            }
        }
        __syncthreads();                                  // seal before buffer reuse
    }
}

// ---------------------------------------------------------------------------
// K2: QKV projection. grid (6, NTOK/128). nb 0-1: Q, 2-3: K, 4-5: V.
// ---------------------------------------------------------------------------
__global__ void __launch_bounds__(256, 2)
qkv_gemm_kernel(const float* __restrict__ scale)
{
    extern __shared__ char smc[];
    const uint32_t sbase = s2u(smc);
    const int tid = threadIdx.x, wid = tid >> 5, lane = tid & 31;
    const int nb = blockIdx.x;
    const int m0 = blockIdx.y * 128;

    float acc[2][8][4] = {};
    gemm_mainloop128(sbase,
                     g_xh + (size_t)m0 * 128, g_xl + (size_t)m0 * 128,
                     g_wh + (size_t)(nb * 128) * 128, g_wl + (size_t)(nb * 128) * 128,
                     acc);

    const int wm = (wid & 3) * 32, wn = (wid >> 2) * 64;
    const int g = lane >> 2, tg = lane & 3;

    if (nb < 4) {
        const bool isQ = nb < 2;
        const float mul = isQ ? scale[0] : 1.0f;
        const int pbase = (isQ ? 0 : 128) + (nb & 1) * 64 + wn / 2;
        #pragma unroll
        for (int mi = 0; mi < 2; mi++)
            #pragma unroll
            for (int half = 0; half < 2; half++) {
                const int row = m0 + wm + mi * 16 + g + half * 8;
                uint32_t* dh = &g_qkh[(size_t)row * 256 + pbase];
                uint32_t* dl = &g_qkl[(size_t)row * 256 + pbase];
                #pragma unroll
                for (int nj = 0; nj < 8; nj++) {
                    const float d0 = acc[mi][nj][half * 2]     * mul;
                    const float d1 = acc[mi][nj][half * 2 + 1] * mul;
                    uint32_t lo; const uint32_t hi = bfsplit2(d0, d1, lo);
                    dh[nj * 4 + tg] = hi;
                    dl[nj * 4 + tg] = lo;
                }
            }
    } else {
        const int cbase = (nb & 1) * 128 + wn;
        #pragma unroll
        for (int mi = 0; mi < 2; mi++)
            #pragma unroll
            for (int half = 0; half < 2; half++) {
                const int row = m0 + wm + mi * 16 + g + half * 8;
                #pragma unroll
                for (int nj = 0; nj < 8; nj++) {
                    const int c = cbase + nj * 8 + 2 * tg;
                    *reinterpret_cast<float2*>(&g_v[(size_t)row * 256 + c]) = make_float2(
                        __uint_as_float(f2tf(acc[mi][nj][half * 2])),
                        __uint_as_float(f2tf(acc[mi][nj][half * 2 + 1])));
                }
            }
    }
}

// ---------------------------------------------------------------------------
// K3: per-window attention (unchanged from R13; verified).
// ---------------------------------------------------------------------------
#define AQ_H 0
#define AQ_L 5120
#define AK_H 10240
#define AK_L 15360
#define AVT  20480
#define ASS  29312
#define AT_SMEM 46720

__global__ void __launch_bounds__(256)
attn_kernel(const float* __restrict__ pos)
{
    extern __shared__ char smc[];
    const uint32_t sbase = s2u(smc);
    float* VT = reinterpret_cast<float*>(smc + AVT);   // [32][69]
    float* SS = reinterpret_cast<float*>(smc + ASS);   // [64][68]

    const int tid = threadIdx.x;
    const int wid = tid >> 5, lane = tid & 31;
    const int g = lane >> 2, tg = lane & 3;
    const int m0 = blockIdx.x * NT;

    const int mtile = wid >> 1;
    const int ms = mtile * 16;
    const int nq = (wid & 1) * 4;
    const int np = (wid & 1) * 2;
    const int lrow = lane & 7, seg = lane >> 3;

    for (int h = 0; h < NHEAD; h++) {
        __syncthreads();
        for (int i = tid; i < 512; i += 256) {
            const int isK = i >> 8;
            const int r = (i >> 2) & 63, gc = i & 3;
            const size_t gs = (size_t)(m0 + r) * 256 + (isK ? 128 : 0) + h * 16 + gc * 4;
            const uint32_t so = r * 80 + gc * 16;
            *reinterpret_cast<uint4*>(smc + (isK ? AK_H : AQ_H) + so) =
                *reinterpret_cast<const uint4*>(g_qkh + gs);
            *reinterpret_cast<uint4*>(smc + (isK ? AK_L : AQ_L) + so) =
                *reinterpret_cast<const uint4*>(g_qkl + gs);
        }
        for (int idx = tid; idx < 2048; idx += 256) {
            const int t = idx >> 5, d = idx & 31;
            VT[d * 69 + t] = g_v[(size_t)(m0 + t) * 256 + h * 32 + d];
        }
        __syncthreads();

        float sacc[4][4];
        #pragma unroll
        for (int j = 0; j < 4; j++)
            #pragma unroll
            for (int z = 0; z < 4; z++) sacc[j][z] = 0.f;

        #pragma unroll
        for (int ks = 0; ks < 2; ks++) {
            const int gA = 2 * ks + (seg >> 1);
            const int gB = 2 * ks + (seg & 1);
            const int qrow = ms + (seg & 1) * 8 + lrow;
            uint4 qh, ql;
            ldmx4(qh, sbase + AQ_H + qrow * 80 + gA * 16);
            ldmx4(ql, sbase + AQ_L + qrow * 80 + gA * 16);
            #pragma unroll
            for (int jj = 0; jj < 2; jj++) {
                const int krow = (nq + 2 * jj) * 8 + (seg >> 1) * 8 + lrow;
                uint4 kh, kl;
                ldmx4(kh, sbase + AK_H + krow * 80 + gB * 16);
                ldmx4(kl, sbase + AK_L + krow * 80 + gB * 16);
                mma_bf16(sacc[2 * jj],     qh, kh.x, kh.y);
                mma_bf16(sacc[2 * jj],     ql, kh.x, kh.y);
                mma_bf16(sacc[2 * jj],     qh, kl.x, kl.y);
                mma_bf16(sacc[2 * jj + 1], qh, kh.z, kh.w);
                mma_bf16(sacc[2 * jj + 1], ql, kh.z, kh.w);
                mma_bf16(sacc[2 * jj + 1], qh, kl.z, kl.w);
            }
        }
        #pragma unroll
        for (int j = 0; j < 4; j++) {
            const int c = (nq + j) * 8 + 2 * tg;
            const int row = ms + g;
            const float2 pv0 = *reinterpret_cast<const float2*>(
                &pos[h * 4096 + row * 64 + c]);
            *reinterpret_cast<float2*>(&SS[row * 68 + c]) =
                make_float2(sacc[j][0] + pv0.x, sacc[j][1] + pv0.y);
            const float2 pv1 = *reinterpret_cast<const float2*>(
                &pos[h * 4096 + (row + 8) * 64 + c]);
            *reinterpret_cast<float2*>(&SS[(row + 8) * 68 + c]) =
                make_float2(sacc[j][2] + pv1.x, sacc[j][3] + pv1.y);
        }
        __syncthreads();

        if (tid < 128) {
            const int row = tid >> 1, half = tid & 1;
            float* p = &SS[row * 68 + half * 32];
            float m = -1e30f;
            #pragma unroll 8
            for (int j = 0; j < 32; j++) m = fmaxf(m, p[j]);
            m = fmaxf(m, __shfl_xor_sync(0xFFFFFFFFu, m, 1));
            float s = 0.f;
            #pragma unroll 8
            for (int j = 0; j < 32; j++) { const float e = __expf(p[j] - m); p[j] = e; s += e; }
            s += __shfl_xor_sync(0xFFFFFFFFu, s, 1);
            const float inv = 1.f / s;
            #pragma unroll 8
            for (int j = 0; j < 32; j++)
                p[j] = __uint_as_float(f2tf(p[j] * inv));
        }
        __syncthreads();

        float oacc[2][4];
        #pragma unroll
        for (int j = 0; j < 2; j++)
            #pragma unroll
            for (int z = 0; z < 4; z++) oacc[j][z] = 0.f;

        #pragma unroll
        for (int ks = 0; ks < 8; ks++) {
            const int kk = ks * 8;
            const float* Sp = &SS[(ms + g) * 68 + kk + tg];
            const uint32_t a0 = __float_as_uint(Sp[0]);
            const uint32_t a1 = __float_as_uint(Sp[8 * 68]);
            const uint32_t a2 = __float_as_uint(Sp[4]);
            const uint32_t a3 = __float_as_uint(Sp[8 * 68 + 4]);
            #pragma unroll
            for (int j = 0; j < 2; j++) {
                const float* Vp = &VT[((np + j) * 8 + g) * 69 + kk + tg];
                mma_tf32(oacc[j], a0, a1, a2, a3,
                         __float_as_uint(Vp[0]), __float_as_uint(Vp[4]));
            }
        }
        #pragma unroll
        for (int j = 0; j < 2; j++) {
            const int pb = h * 16 + (np + j) * 4 + tg;
            #pragma unroll
            for (int half = 0; half < 2; half++) {
                const int row = ms + g + half * 8;
                uint32_t lo;
                const uint32_t hi = bfsplit2(oacc[j][half * 2], oacc[j][half * 2 + 1], lo);
                g_ath[(size_t)(m0 + row) * 128 + pb] = hi;
                g_atl[(size_t)(m0 + row) * 128 + pb] = lo;
            }
        }
    }
}

// ---------------------------------------------------------------------------
// K4: output projection (3-term bf16, 128x128 tile) + bias + residual.
// grid (2, NTOK/128).
// ---------------------------------------------------------------------------
__global__ void __launch_bounds__(256, 2)
outproj_gemm_kernel(const float* __restrict__ x, const float* __restrict__ bo,
                    float* __restrict__ out)
{
    extern __shared__ char smc[];
    const uint32_t sbase = s2u(smc);
    const int tid = threadIdx.x, wid = tid >> 5, lane = tid & 31;
    const int nb = blockIdx.x;           // 0..1
    const int m0 = blockIdx.y * 128;

    float acc[2][8][4] = {};
    gemm_mainloop128(sbase,
                     g_ath + (size_t)m0 * 128, g_atl + (size_t)m0 * 128,
                     g_wh + (size_t)(768 + nb * 128) * 128,
                     g_wl + (size_t)(768 + nb * 128) * 128,
                     acc);

    const int wm = (wid & 3) * 32, wn = (wid >> 2) * 64;
    const int g = lane >> 2, tg = lane & 3;
    const int n0 = nb * 128;
    #pragma unroll
    for (int mi = 0; mi < 2; mi++) {
        #pragma unroll
        for (int half = 0; half < 2; half++) {
            const int r = wm + mi * 16 + g + half * 8;
            int b, pix; tok2pix(m0 + r, b, pix);
            const size_t base = (size_t)b * CH * IMG * IMG + pix;
            #pragma unroll
            for (int nj = 0; nj < 8; nj++) {
                const int c0 = n0 + wn + nj * 8 + 2 * tg;
                const size_t a0 = base + (size_t)c0 * (IMG * IMG);
                const size_t a1 = a0 + (IMG * IMG);
                out[a0] = acc[mi][nj][half * 2 + 0] + bo[c0]     + x[a0];
                out[a1] = acc[mi][nj][half * 2 + 1] + bo[c0 + 1] + x[a1];
            }
        }
    }
}

// ---------------------------------------------------------------------------
extern "C" void kernel_launch(void* const* d_in, const int* in_sizes, int n_in,
                              void* d_out, int out_size)
{
    const float* x    = (const float*)d_in[0];
    const float* gnw  = (const float*)d_in[1];
    const float* gnb  = (const float*)d_in[2];
    const float* Wq   = (const float*)d_in[3];
    const float* Wk   = (const float*)d_in[4];
    const float* Wv   = (const float*)d_in[5];
    const float* Wo   = (const float*)d_in[6];
    const float* bo   = (const float*)d_in[7];
    const float* pos  = (const float*)d_in[8];
    const float* scl  = (const float*)d_in[9];
    float* out = (float*)d_out;

    cudaFuncSetAttribute(qkv_gemm_kernel,     cudaFuncAttributeMaxDynamicSharedMemorySize, GM_SMEM);
    cudaFuncSetAttribute(outproj_gemm_kernel, cudaFuncAttributeMaxDynamicSharedMemorySize, GM_SMEM);
    cudaFuncSetAttribute(attn_kernel,         cudaFuncAttributeMaxDynamicSharedMemorySize, AT_SMEM);

    gn_stats_kernel<<<BATCH * 32, 512>>>(x);
    prep_w_kernel<<<512, 256>>>(Wq, Wk, Wv, Wo);
    prep_x_kernel<<<NTOK / 128, 256>>>(x, gnw, gnb);
    qkv_gemm_kernel<<<dim3(6, NTOK / 128), 256, GM_SMEM>>>(scl);
    attn_kernel<<<NTOK / NT, 256, AT_SMEM>>>(pos);
    outproj_gemm_kernel<<<dim3(2, NTOK / 128), 256, GM_SMEM>>>(x, bo, out);
}

// round 15
// speedup vs baseline: 1.0702x; 1.0702x over previous
#include <cuda_runtime.h>
#include <cuda_bf16.h>
#include <cstdint>

#define BATCH  4
#define CH     256
#define IMG    256
#define WSZ    8
#define NT     64
#define NHEAD  8
#define GN_EPS 1e-5f
#define NTOK   (BATCH * IMG * IMG)          // 262144

// ---- device-global scratch (allocation is banned) ----
__device__ float    g_mean[BATCH * 32];
__device__ float    g_rstd[BATCH * 32];
__device__ uint32_t g_xh[(size_t)NTOK * 128];   // GN(x) bf16x2 hi, [token][128]
__device__ uint32_t g_xl[(size_t)NTOK * 128];   // lo residual
__device__ uint32_t g_wh[1024 * 128];           // Wq|Wk|Wv|Wo rows, bf16x2 hi
__device__ uint32_t g_wl[1024 * 128];
__device__ uint32_t g_qkh[(size_t)NTOK * 256];  // [token][Q 128 pairs | K 128 pairs] hi
__device__ uint32_t g_qkl[(size_t)NTOK * 256];
__device__ float    g_v  [(size_t)NTOK * 256];  // V, tf32-rounded fp32
__device__ uint32_t g_ath[(size_t)NTOK * 128];  // attention out, split bf16
__device__ uint32_t g_atl[(size_t)NTOK * 128];

// ---------------------------------------------------------------------------
// helpers
// ---------------------------------------------------------------------------
__device__ __forceinline__ uint32_t f2tf(float f) {
    uint32_t u; asm("cvt.rna.tf32.f32 %0, %1;" : "=r"(u) : "f"(f)); return u;
}
__device__ __forceinline__ void mma_tf32(float d[4],
    uint32_t a0, uint32_t a1, uint32_t a2, uint32_t a3,
    uint32_t b0, uint32_t b1)
{
    asm("mma.sync.aligned.m16n8k8.row.col.f32.tf32.tf32.f32 "
        "{%0,%1,%2,%3},{%4,%5,%6,%7},{%8,%9},{%0,%1,%2,%3};"
        : "+f"(d[0]), "+f"(d[1]), "+f"(d[2]), "+f"(d[3])
        : "r"(a0), "r"(a1), "r"(a2), "r"(a3), "r"(b0), "r"(b1));
}
__device__ __forceinline__ void mma_bf16(float d[4], uint4 a, uint32_t b0, uint32_t b1)
{
    asm("mma.sync.aligned.m16n8k16.row.col.f32.bf16.bf16.f32 "
        "{%0,%1,%2,%3},{%4,%5,%6,%7},{%8,%9},{%0,%1,%2,%3};"
        : "+f"(d[0]), "+f"(d[1]), "+f"(d[2]), "+f"(d[3])
        : "r"(a.x), "r"(a.y), "r"(a.z), "r"(a.w), "r"(b0), "r"(b1));
}
__device__ __forceinline__ void ldmx4(uint4& d, uint32_t addr) {
    asm volatile("ldmatrix.sync.aligned.m8n8.x4.shared.b16 {%0,%1,%2,%3}, [%4];"
        : "=r"(d.x), "=r"(d.y), "=r"(d.z), "=r"(d.w) : "r"(addr));
}
__device__ __forceinline__ uint32_t s2u(const void* p) {
    uint32_t a;
    asm("{ .reg .u64 t; cvta.to.shared.u64 t, %1; cvt.u32.u64 %0, t; }" : "=r"(a) : "l"(p));
    return a;
}
__device__ __forceinline__ void cpa16(uint32_t saddr, const void* gptr) {
    asm volatile("cp.async.cg.shared.global [%0], [%1], 16;" :: "r"(saddr), "l"(gptr));
}
__device__ __forceinline__ void tok2pix(int m, int& b, int& pix) {
    b = m >> 16;
    const int win = (m >> 6) & 1023;
    const int t   = m & 63;
    pix = ((win >> 5) * WSZ + (t >> 3)) * IMG + (win & 31) * WSZ + (t & 7);
}
__device__ __forceinline__ uint32_t bfsplit2(float a, float b, uint32_t& lo) {
    __nv_bfloat16 ah = __float2bfloat16(a);
    __nv_bfloat16 bh = __float2bfloat16(b);
    __nv_bfloat16 al = __float2bfloat16(a - __bfloat162float(ah));
    __nv_bfloat16 bl = __float2bfloat16(b - __bfloat162float(bh));
    lo = (uint32_t)__bfloat16_as_ushort(al) | ((uint32_t)__bfloat16_as_ushort(bl) << 16);
    return (uint32_t)__bfloat16_as_ushort(ah) | ((uint32_t)__bfloat16_as_ushort(bh) << 16);
}

// ---------------------------------------------------------------------------
// K1: GroupNorm statistics
// ---------------------------------------------------------------------------
__global__ void gn_stats_kernel(const float* __restrict__ x)
{
    const int bg = blockIdx.x;
    const float4* p = reinterpret_cast<const float4*>(x + (size_t)bg * 8 * IMG * IMG);
    const int n4 = (8 * IMG * IMG) / 4;

    float s = 0.f, sq = 0.f;
    for (int i = threadIdx.x; i < n4; i += blockDim.x) {
        float4 v = p[i];
        s  += v.x + v.y + v.z + v.w;
        sq += v.x * v.x + v.y * v.y + v.z * v.z + v.w * v.w;
    }
    for (int o = 16; o; o >>= 1) {
        s  += __shfl_down_sync(0xFFFFFFFFu, s,  o);
        sq += __shfl_down_sync(0xFFFFFFFFu, sq, o);
    }
    __shared__ float ss[32], ssq[32];
    const int w = threadIdx.x >> 5, l = threadIdx.x & 31;
    if (l == 0) { ss[w] = s; ssq[w] = sq; }
    __syncthreads();
    if (w == 0) {
        const int nw = blockDim.x >> 5;
        s  = (l < nw) ? ss[l]  : 0.f;
        sq = (l < nw) ? ssq[l] : 0.f;
        for (int o = 16; o; o >>= 1) {
            s  += __shfl_down_sync(0xFFFFFFFFu, s,  o);
            sq += __shfl_down_sync(0xFFFFFFFFu, sq, o);
        }
        if (l == 0) {
            const float invN = 1.f / (float)(8 * IMG * IMG);
            const float m   = s * invN;
            const float var = sq * invN - m * m;
            g_mean[bg] = m;
            g_rstd[bg] = rsqrtf(var + GN_EPS);
        }
    }
}

// ---------------------------------------------------------------------------
// K0a: split all weights once (Wq|Wk|Wv|Wo -> rows 0..1023)
// ---------------------------------------------------------------------------
__global__ void prep_w_kernel(const float* __restrict__ Wq, const float* __restrict__ Wk,
                              const float* __restrict__ Wv, const float* __restrict__ Wo)
{
    const int idx = blockIdx.x * 256 + threadIdx.x;     // 0..131071
    const int r = idx >> 7, p = idx & 127;
    const float* W = (r < 256) ? Wq : ((r < 512) ? Wk : ((r < 768) ? Wv : Wo));
    const float2 w = *reinterpret_cast<const float2*>(&W[(size_t)(r & 255) * 256 + 2 * p]);
    uint32_t lo; const uint32_t hi = bfsplit2(w.x, w.y, lo);
    g_wh[idx] = hi; g_wl[idx] = lo;
}

// ---------------------------------------------------------------------------
// K0b: GN + bf16 split of x, once, token-major. 128 tokens per block.
// ---------------------------------------------------------------------------
__global__ void prep_x_kernel(const float* __restrict__ x,
                              const float* __restrict__ gnw, const float* __restrict__ gnb)
{
    __shared__ uint32_t Sh[128][17], Sl[128][17];
    const int tid = threadIdx.x;
    const int m0 = blockIdx.x * 128;

    for (int slab = 0; slab < 8; slab++) {
        __syncthreads();
        for (int i = tid; i < 2048; i += 256) {
            const int tok = i & 127, p = i >> 7;        // p 0..15
            const int c = slab * 32 + 2 * p;
            int bb, pix; tok2pix(m0 + tok, bb, pix);
            const size_t base = (size_t)bb * CH * IMG * IMG + pix;
            const float v0 = x[base + (size_t)c * (IMG * IMG)];
            const float v1 = x[base + (size_t)(c + 1) * (IMG * IMG)];
            const float mn = g_mean[bb * 32 + (c >> 3)];
            const float rs = g_rstd[bb * 32 + (c >> 3)];
            const float a = (v0 - mn) * rs * gnw[c]     + gnb[c];
            const float d = (v1 - mn) * rs * gnw[c + 1] + gnb[c + 1];
            uint32_t lo; const uint32_t hi = bfsplit2(a, d, lo);
            Sh[tok][p] = hi; Sl[tok][p] = lo;
        }
        __syncthreads();
        for (int i = tid; i < 2048; i += 256) {
            const int tok = i >> 4, p = i & 15;
            g_xh[(size_t)(m0 + tok) * 128 + slab * 16 + p] = Sh[tok][p];
            g_xl[(size_t)(m0 + tok) * 128 + slab * 16 + p] = Sl[tok][p];
        }
    }
}

// ---------------------------------------------------------------------------
// Shared GEMM mainloop (R13 known-good): C[128,128] += A[128,256]*B[128,256]^T,
// 3-term split-bf16. Single-stage cp.async fills (K chunk 64), ldmatrix frags,
// warp tile 32m x 64n, 64KB smem, 2 CTAs/SM.
// ---------------------------------------------------------------------------
#define SA_H 0
#define SA_L 16384
#define SB_H 32768
#define SB_L 49152
#define GM_SMEM 65536

__device__ __forceinline__ void gemm_mainloop128(
    uint32_t sbase,
    const uint32_t* __restrict__ Ah_g, const uint32_t* __restrict__ Al_g,
    const uint32_t* __restrict__ Bh_g, const uint32_t* __restrict__ Bl_g,
    float acc[2][8][4])
{
    const int tid = threadIdx.x, wid = tid >> 5, lane = tid & 31;
    const int wm = (wid & 3) * 32, wn = (wid >> 2) * 64;
    const int lrow = lane & 7, seg = lane >> 3;
    const int arow = wm + (seg & 1) * 8 + lrow;          // + mi*16
    const int brow = wn + (seg >> 1) * 8 + lrow;         // + half*32 + jj*16
    const int agc = seg >> 1;                            // + 2ks
    const int bgc = seg & 1;

    for (int kc = 0; kc < 4; kc++) {
        __syncthreads();
        #pragma unroll
        for (int i = tid; i < 1024; i += 256) {
            const int r = i >> 3, gc = i & 7;
            const size_t gs = (size_t)r * 128 + kc * 32 + gc * 4;
            const uint32_t so = r * 128 + ((gc ^ (r & 7)) << 4);
            cpa16(sbase + SA_H + so, Ah_g + gs);
            cpa16(sbase + SA_L + so, Al_g + gs);
            cpa16(sbase + SB_H + so, Bh_g + gs);
            cpa16(sbase + SB_L + so, Bl_g + gs);
        }
        asm volatile("cp.async.commit_group;");
        asm volatile("cp.async.wait_group 0;" ::: "memory");
        __syncthreads();
        #pragma unroll
        for (int ks = 0; ks < 4; ks++) {
            const int gA = 2 * ks + agc;
            const int gB = 2 * ks + bgc;
            uint4 ah[2], al[2];
            #pragma unroll
            for (int mi = 0; mi < 2; mi++) {
                const int r = arow + mi * 16;
                const uint32_t ad = sbase + SA_H + r * 128 + ((gA ^ (r & 7)) << 4);
                ldmx4(ah[mi], ad);
                ldmx4(al[mi], ad + (SA_L - SA_H));
            }
            #pragma unroll
            for (int half = 0; half < 2; half++) {
                uint4 bh[2], bl[2];
                #pragma unroll
                for (int jj = 0; jj < 2; jj++) {
                    const int r = brow + half * 32 + jj * 16;
                    const uint32_t bd = sbase + SB_H + r * 128 + ((gB ^ (r & 7)) << 4);
                    ldmx4(bh[jj], bd);
                    ldmx4(bl[jj], bd + (SB_L - SB_H));
                }
                #pragma unroll
                for (int jj = 0; jj < 2; jj++) {
                    const int n0 = half * 4 + 2 * jj;
                    #pragma unroll
                    for (int mi = 0; mi < 2; mi++) {
                        mma_bf16(acc[mi][n0],     ah[mi], bh[jj].x, bh[jj].y);
                        mma_bf16(acc[mi][n0],     al[mi], bh[jj].x, bh[jj].y);
                        mma_bf16(acc[mi][n0],     ah[mi], bl[jj].x, bl[jj].y);
                        mma_bf16(acc[mi][n0 + 1], ah[mi], bh[jj].z, bh[jj].w);
                        mma_bf16(acc[mi][n0 + 1], al[mi], bh[jj].z, bh[jj].w);
                        mma_bf16(acc[mi][n0 + 1], ah[mi], bl[jj].z, bl[jj].w);
                    }
                }
            }
        }
    }
}

// ---------------------------------------------------------------------------
// K2: QKV projection. grid (6, NTOK/128). nb 0-1: Q, 2-3: K, 4-5: V.
// ---------------------------------------------------------------------------
__global__ void __launch_bounds__(256, 2)
qkv_gemm_kernel(const float* __restrict__ scale)
{
    extern __shared__ char smc[];
    const uint32_t sbase = s2u(smc);
    const int tid = threadIdx.x, wid = tid >> 5, lane = tid & 31;
    const int nb = blockIdx.x;
    const int m0 = blockIdx.y * 128;

    float acc[2][8][4] = {};
    gemm_mainloop128(sbase,
                     g_xh + (size_t)m0 * 128, g_xl + (size_t)m0 * 128,
                     g_wh + (size_t)(nb * 128) * 128, g_wl + (size_t)(nb * 128) * 128,
                     acc);

    const int wm = (wid & 3) * 32, wn = (wid >> 2) * 64;
    const int g = lane >> 2, tg = lane & 3;

    if (nb < 4) {
        const bool isQ = nb < 2;
        const float mul = isQ ? scale[0] : 1.0f;
        const int pbase = (isQ ? 0 : 128) + (nb & 1) * 64 + wn / 2;
        #pragma unroll
        for (int mi = 0; mi < 2; mi++)
            #pragma unroll
            for (int half = 0; half < 2; half++) {
                const int row = m0 + wm + mi * 16 + g + half * 8;
                uint32_t* dh = &g_qkh[(size_t)row * 256 + pbase];
                uint32_t* dl = &g_qkl[(size_t)row * 256 + pbase];
                #pragma unroll
                for (int nj = 0; nj < 8; nj++) {
                    const float d0 = acc[mi][nj][half * 2]     * mul;
                    const float d1 = acc[mi][nj][half * 2 + 1] * mul;
                    uint32_t lo; const uint32_t hi = bfsplit2(d0, d1, lo);
                    dh[nj * 4 + tg] = hi;
                    dl[nj * 4 + tg] = lo;
                }
            }
    } else {
        const int cbase = (nb & 1) * 128 + wn;
        #pragma unroll
        for (int mi = 0; mi < 2; mi++)
            #pragma unroll
            for (int half = 0; half < 2; half++) {
                const int row = m0 + wm + mi * 16 + g + half * 8;
                #pragma unroll
                for (int nj = 0; nj < 8; nj++) {
                    const int c = cbase + nj * 8 + 2 * tg;
                    *reinterpret_cast<float2*>(&g_v[(size_t)row * 256 + c]) = make_float2(
                        __uint_as_float(f2tf(acc[mi][nj][half * 2])),
                        __uint_as_float(f2tf(acc[mi][nj][half * 2 + 1])));
                }
            }
    }
}

// ---------------------------------------------------------------------------
// K3: per-window attention, TWO heads per iteration.
// Per-head-side region (stride 29312B): QH 0 | QL 5120 | KH 10240 | KL 15360
// | VT 20480 (32x69 f32). SS: two 64x68 f32 regions at 58624.
// Warp wid handles head side s=wid&1, rows ms=(wid>>1)*16..+15, full columns.
// Softmax uses all 256 threads (128 row-halves x 2 heads).
// Math identical to R13 per output element -> rel_err must be 1.6748e-4.
// ---------------------------------------------------------------------------
#define HP_QKV 29312
#define HP_VT  20480
#define A2_SS  58624
#define HP_SS  17408
#define AT_SMEM (A2_SS + 2 * HP_SS)   // 93440

__global__ void __launch_bounds__(256)
attn_kernel(const float* __restrict__ pos)
{
    extern __shared__ char smc[];
    const uint32_t sbase = s2u(smc);

    const int tid = threadIdx.x;
    const int wid = tid >> 5, lane = tid & 31;
    const int g = lane >> 2, tg = lane & 3;
    const int lrow = lane & 7, seg = lane >> 3;
    const int m0 = blockIdx.x * NT;

    const int s  = wid & 1;                 // head side for this warp
    const int ms = (wid >> 1) * 16;         // row strip
    const uint32_t qkvb = sbase + s * HP_QKV;
    float* VTs = reinterpret_cast<float*>(smc + s * HP_QKV + HP_VT);
    float* SSs = reinterpret_cast<float*>(smc + A2_SS + s * HP_SS);

    for (int hp = 0; hp < 4; hp++) {
        const int h = 2 * hp + s;
        __syncthreads();
        // ---- fills for BOTH heads ----
        for (int i = tid; i < 1024; i += 256) {
            const int fs = i >> 9, i2 = i & 511;
            const int isK = i2 >> 8, r = (i2 >> 2) & 63, gc = i2 & 3;
            const size_t gs = (size_t)(m0 + r) * 256 + (isK ? 128 : 0)
                            + (2 * hp + fs) * 16 + gc * 4;
            const uint32_t so = fs * HP_QKV + (isK ? 10240u : 0u) + r * 80 + gc * 16;
            *reinterpret_cast<uint4*>(smc + so) =
                *reinterpret_cast<const uint4*>(g_qkh + gs);
            *reinterpret_cast<uint4*>(smc + so + 5120) =
                *reinterpret_cast<const uint4*>(g_qkl + gs);
        }
        for (int i = tid; i < 1024; i += 256) {
            const int fs = i >> 9, i2 = i & 511;
            const int tok = i2 >> 3, d4 = (i2 & 7) * 4;
            const float4 v = *reinterpret_cast<const float4*>(
                &g_v[(size_t)(m0 + tok) * 256 + (2 * hp + fs) * 32 + d4]);
            float* vt = reinterpret_cast<float*>(smc + fs * HP_QKV + HP_VT);
            vt[(d4 + 0) * 69 + tok] = v.x;
            vt[(d4 + 1) * 69 + tok] = v.y;
            vt[(d4 + 2) * 69 + tok] = v.z;
            vt[(d4 + 3) * 69 + tok] = v.w;
        }
        __syncthreads();

        // ---- S = Q K^T (3-term bf16): warp covers 16 rows x 64 cols ----
        float sacc[8][4];
        #pragma unroll
        for (int j = 0; j < 8; j++)
            #pragma unroll
            for (int z = 0; z < 4; z++) sacc[j][z] = 0.f;

        #pragma unroll
        for (int ks = 0; ks < 2; ks++) {
            const int gA = 2 * ks + (seg >> 1);
            const int gB = 2 * ks + (seg & 1);
            const int qrow = ms + (seg & 1) * 8 + lrow;
            uint4 qh, ql;
            ldmx4(qh, qkvb + qrow * 80 + gA * 16);
            ldmx4(ql, qkvb + 5120 + qrow * 80 + gA * 16);
            #pragma unroll
            for (int jj = 0; jj < 4; jj++) {
                const int krow = jj * 16 + (seg >> 1) * 8 + lrow;
                uint4 kh, kl;
                ldmx4(kh, qkvb + 10240 + krow * 80 + gB * 16);
                ldmx4(kl, qkvb + 15360 + krow * 80 + gB * 16);
                mma_bf16(sacc[2 * jj],     qh, kh.x, kh.y);
                mma_bf16(sacc[2 * jj],     ql, kh.x, kh.y);
                mma_bf16(sacc[2 * jj],     qh, kl.x, kl.y);
                mma_bf16(sacc[2 * jj + 1], qh, kh.z, kh.w);
                mma_bf16(sacc[2 * jj + 1], ql, kh.z, kh.w);
                mma_bf16(sacc[2 * jj + 1], qh, kl.z, kl.w);
            }
        }
        // SS = sacc + pos
        #pragma unroll
        for (int j = 0; j < 8; j++) {
            const int c = j * 8 + 2 * tg;
            const int row = ms + g;
            const float2 pv0 = *reinterpret_cast<const float2*>(
                &pos[h * 4096 + row * 64 + c]);
            *reinterpret_cast<float2*>(&SSs[row * 68 + c]) =
                make_float2(sacc[j][0] + pv0.x, sacc[j][1] + pv0.y);
            const float2 pv1 = *reinterpret_cast<const float2*>(
                &pos[h * 4096 + (row + 8) * 64 + c]);
            *reinterpret_cast<float2*>(&SSs[(row + 8) * 68 + c]) =
                make_float2(sacc[j][2] + pv1.x, sacc[j][3] + pv1.y);
        }
        __syncthreads();

        // ---- softmax: ALL 256 threads (2 heads x 64 rows x 2 halves) ----
        {
            const int rg = tid >> 1, half = tid & 1;
            const int hs = rg >> 6, row = rg & 63;
            float* p = reinterpret_cast<float*>(smc + A2_SS + hs * HP_SS)
                     + row * 68 + half * 32;
            float m = -1e30f;
            #pragma unroll 8
            for (int j = 0; j < 32; j++) m = fmaxf(m, p[j]);
            m = fmaxf(m, __shfl_xor_sync(0xFFFFFFFFu, m, 1));
            float sum = 0.f;
            #pragma unroll 8
            for (int j = 0; j < 32; j++) { const float e = __expf(p[j] - m); p[j] = e; sum += e; }
            sum += __shfl_xor_sync(0xFFFFFFFFu, sum, 1);
            const float inv = 1.f / sum;
            #pragma unroll 8
            for (int j = 0; j < 32; j++)
                p[j] = __uint_as_float(f2tf(p[j] * inv));
        }
        __syncthreads();

        // ---- O = S @ V (tf32): warp covers 16 rows x 32 cols ----
        float oacc[4][4];
        #pragma unroll
        for (int j = 0; j < 4; j++)
            #pragma unroll
            for (int z = 0; z < 4; z++) oacc[j][z] = 0.f;

        #pragma unroll
        for (int ks = 0; ks < 8; ks++) {
            const int kk = ks * 8;
            const float* Sp = &SSs[(ms + g) * 68 + kk + tg];
            const uint32_t a0 = __float_as_uint(Sp[0]);
            const uint32_t a1 = __float_as_uint(Sp[8 * 68]);
            const uint32_t a2 = __float_as_uint(Sp[4]);
            const uint32_t a3 = __float_as_uint(Sp[8 * 68 + 4]);
            #pragma unroll
            for (int j = 0; j < 4; j++) {
                const float* Vp = &VTs[(j * 8 + g) * 69 + kk + tg];
                mma_tf32(oacc[j], a0, a1, a2, a3,
                         __float_as_uint(Vp[0]), __float_as_uint(Vp[4]));
            }
        }
        #pragma unroll
        for (int j = 0; j < 4; j++) {
            const int pb = h * 16 + j * 4 + tg;
            #pragma unroll
            for (int half = 0; half < 2; half++) {
                const int row = ms + g + half * 8;
                uint32_t lo;
                const uint32_t hi = bfsplit2(oacc[j][half * 2], oacc[j][half * 2 + 1], lo);
                g_ath[(size_t)(m0 + row) * 128 + pb] = hi;
                g_atl[(size_t)(m0 + row) * 128 + pb] = lo;
            }
        }
    }
}

// ---------------------------------------------------------------------------
// K4: output projection (3-term bf16, 128x128 tile) + bias + residual.
// grid (2, NTOK/128).
// ---------------------------------------------------------------------------
__global__ void __launch_bounds__(256, 2)
outproj_gemm_kernel(const float* __restrict__ x, const float* __restrict__ bo,
                    float* __restrict__ out)
{
    extern __shared__ char smc[];
    const uint32_t sbase = s2u(smc);
    const int tid = threadIdx.x, wid = tid >> 5, lane = tid & 31;
    const int nb = blockIdx.x;           // 0..1
    const int m0 = blockIdx.y * 128;

    float acc[2][8][4] = {};
    gemm_mainloop128(sbase,
                     g_ath + (size_t)m0 * 128, g_atl + (size_t)m0 * 128,
                     g_wh + (size_t)(768 + nb * 128) * 128,
                     g_wl + (size_t)(768 + nb * 128) * 128,
                     acc);

    const int wm = (wid & 3) * 32, wn = (wid >> 2) * 64;
    const int g = lane >> 2, tg = lane & 3;
    const int n0 = nb * 128;
    #pragma unroll
    for (int mi = 0; mi < 2; mi++) {
        #pragma unroll
        for (int half = 0; half < 2; half++) {
            const int r = wm + mi * 16 + g + half * 8;
            int b, pix; tok2pix(m0 + r, b, pix);
            const size_t base = (size_t)b * CH * IMG * IMG + pix;
            #pragma unroll
            for (int nj = 0; nj < 8; nj++) {
                const int c0 = n0 + wn + nj * 8 + 2 * tg;
                const size_t a0 = base + (size_t)c0 * (IMG * IMG);
                const size_t a1 = a0 + (IMG * IMG);
                out[a0] = acc[mi][nj][half * 2 + 0] + bo[c0]     + x[a0];
                out[a1] = acc[mi][nj][half * 2 + 1] + bo[c0 + 1] + x[a1];
            }
        }
    }
}

// ---------------------------------------------------------------------------
extern "C" void kernel_launch(void* const* d_in, const int* in_sizes, int n_in,
                              void* d_out, int out_size)
{
    const float* x    = (const float*)d_in[0];
    const float* gnw  = (const float*)d_in[1];
    const float* gnb  = (const float*)d_in[2];
    const float* Wq   = (const float*)d_in[3];
    const float* Wk   = (const float*)d_in[4];
    const float* Wv   = (const float*)d_in[5];
    const float* Wo   = (const float*)d_in[6];
    const float* bo   = (const float*)d_in[7];
    const float* pos  = (const float*)d_in[8];
    const float* scl  = (const float*)d_in[9];
    float* out = (float*)d_out;

    cudaFuncSetAttribute(qkv_gemm_kernel,     cudaFuncAttributeMaxDynamicSharedMemorySize, GM_SMEM);
    cudaFuncSetAttribute(outproj_gemm_kernel, cudaFuncAttributeMaxDynamicSharedMemorySize, GM_SMEM);
    cudaFuncSetAttribute(attn_kernel,         cudaFuncAttributeMaxDynamicSharedMemorySize, AT_SMEM);

    gn_stats_kernel<<<BATCH * 32, 512>>>(x);
    prep_w_kernel<<<512, 256>>>(Wq, Wk, Wv, Wo);
    prep_x_kernel<<<NTOK / 128, 256>>>(x, gnw, gnb);
    qkv_gemm_kernel<<<dim3(6, NTOK / 128), 256, GM_SMEM>>>(scl);
    attn_kernel<<<NTOK / NT, 256, AT_SMEM>>>(pos);
    outproj_gemm_kernel<<<dim3(2, NTOK / 128), 256, GM_SMEM>>>(x, bo, out);
}

// round 16
// speedup vs baseline: 1.1763x; 1.0992x over previous
#include <cuda_runtime.h>
#include <cuda_bf16.h>
#include <cstdint>

#define BATCH  4
#define CH     256
#define IMG    256
#define WSZ    8
#define NT     64
#define NHEAD  8
#define GN_EPS 1e-5f
#define NTOK   (BATCH * IMG * IMG)          // 262144

// ---- device-global scratch (allocation is banned) ----
__device__ float    g_mean[BATCH * 32];
__device__ float    g_rstd[BATCH * 32];
__device__ uint32_t g_xh[(size_t)NTOK * 128];   // GN(x) bf16x2 hi, [token][128]
__device__ uint32_t g_xl[(size_t)NTOK * 128];   // lo residual
__device__ uint32_t g_wh[1024 * 128];           // Wq|Wk|Wv|Wo rows, bf16x2 hi
__device__ uint32_t g_wl[1024 * 128];
__device__ uint32_t g_qkh[(size_t)NTOK * 256];  // [token][Q 128 pairs | K 128 pairs] hi
__device__ uint32_t g_qkl[(size_t)NTOK * 256];
__device__ float    g_v  [(size_t)NTOK * 256];  // V, tf32-rounded fp32
__device__ uint32_t g_ath[(size_t)NTOK * 128];  // attention out, split bf16
__device__ uint32_t g_atl[(size_t)NTOK * 128];

// ---------------------------------------------------------------------------
// helpers
// ---------------------------------------------------------------------------
__device__ __forceinline__ uint32_t f2tf(float f) {
    uint32_t u; asm("cvt.rna.tf32.f32 %0, %1;" : "=r"(u) : "f"(f)); return u;
}
__device__ __forceinline__ void mma_tf32(float d[4],
    uint32_t a0, uint32_t a1, uint32_t a2, uint32_t a3,
    uint32_t b0, uint32_t b1)
{
    asm("mma.sync.aligned.m16n8k8.row.col.f32.tf32.tf32.f32 "
        "{%0,%1,%2,%3},{%4,%5,%6,%7},{%8,%9},{%0,%1,%2,%3};"
        : "+f"(d[0]), "+f"(d[1]), "+f"(d[2]), "+f"(d[3])
        : "r"(a0), "r"(a1), "r"(a2), "r"(a3), "r"(b0), "r"(b1));
}
__device__ __forceinline__ void mma_bf16(float d[4], uint4 a, uint32_t b0, uint32_t b1)
{
    asm("mma.sync.aligned.m16n8k16.row.col.f32.bf16.bf16.f32 "
        "{%0,%1,%2,%3},{%4,%5,%6,%7},{%8,%9},{%0,%1,%2,%3};"
        : "+f"(d[0]), "+f"(d[1]), "+f"(d[2]), "+f"(d[3])
        : "r"(a.x), "r"(a.y), "r"(a.z), "r"(a.w), "r"(b0), "r"(b1));
}
__device__ __forceinline__ void ldmx4(uint4& d, uint32_t addr) {
    asm volatile("ldmatrix.sync.aligned.m8n8.x4.shared.b16 {%0,%1,%2,%3}, [%4];"
        : "=r"(d.x), "=r"(d.y), "=r"(d.z), "=r"(d.w) : "r"(addr));
}
__device__ __forceinline__ uint32_t s2u(const void* p) {
    uint32_t a;
    asm("{ .reg .u64 t; cvta.to.shared.u64 t, %1; cvt.u32.u64 %0, t; }" : "=r"(a) : "l"(p));
    return a;
}
__device__ __forceinline__ void cpa16(uint32_t saddr, const void* gptr) {
    asm volatile("cp.async.cg.shared.global [%0], [%1], 16;" :: "r"(saddr), "l"(gptr));
}
__device__ __forceinline__ void tok2pix(int m, int& b, int& pix) {
    b = m >> 16;
    const int win = (m >> 6) & 1023;
    const int t   = m & 63;
    pix = ((win >> 5) * WSZ + (t >> 3)) * IMG + (win & 31) * WSZ + (t & 7);
}
__device__ __forceinline__ uint32_t bfsplit2(float a, float b, uint32_t& lo) {
    __nv_bfloat16 ah = __float2bfloat16(a);
    __nv_bfloat16 bh = __float2bfloat16(b);
    __nv_bfloat16 al = __float2bfloat16(a - __bfloat162float(ah));
    __nv_bfloat16 bl = __float2bfloat16(b - __bfloat162float(bh));
    lo = (uint32_t)__bfloat16_as_ushort(al) | ((uint32_t)__bfloat16_as_ushort(bl) << 16);
    return (uint32_t)__bfloat16_as_ushort(ah) | ((uint32_t)__bfloat16_as_ushort(bh) << 16);
}

// ---------------------------------------------------------------------------
// K1: GroupNorm statistics
// ---------------------------------------------------------------------------
__global__ void gn_stats_kernel(const float* __restrict__ x)
{
    const int bg = blockIdx.x;
    const float4* p = reinterpret_cast<const float4*>(x + (size_t)bg * 8 * IMG * IMG);
    const int n4 = (8 * IMG * IMG) / 4;

    float s = 0.f, sq = 0.f;
    for (int i = threadIdx.x; i < n4; i += blockDim.x) {
        float4 v = p[i];
        s  += v.x + v.y + v.z + v.w;
        sq += v.x * v.x + v.y * v.y + v.z * v.z + v.w * v.w;
    }
    for (int o = 16; o; o >>= 1) {
        s  += __shfl_down_sync(0xFFFFFFFFu, s,  o);
        sq += __shfl_down_sync(0xFFFFFFFFu, sq, o);
    }
    __shared__ float ss[32], ssq[32];
    const int w = threadIdx.x >> 5, l = threadIdx.x & 31;
    if (l == 0) { ss[w] = s; ssq[w] = sq; }
    __syncthreads();
    if (w == 0) {
        const int nw = blockDim.x >> 5;
        s  = (l < nw) ? ss[l]  : 0.f;
        sq = (l < nw) ? ssq[l] : 0.f;
        for (int o = 16; o; o >>= 1) {
            s  += __shfl_down_sync(0xFFFFFFFFu, s,  o);
            sq += __shfl_down_sync(0xFFFFFFFFu, sq, o);
        }
        if (l == 0) {
            const float invN = 1.f / (float)(8 * IMG * IMG);
            const float m   = s * invN;
            const float var = sq * invN - m * m;
            g_mean[bg] = m;
            g_rstd[bg] = rsqrtf(var + GN_EPS);
        }
    }
}

// ---------------------------------------------------------------------------
// K0a: split all weights once (Wq|Wk|Wv|Wo -> rows 0..1023)
// ---------------------------------------------------------------------------
__global__ void prep_w_kernel(const float* __restrict__ Wq, const float* __restrict__ Wk,
                              const float* __restrict__ Wv, const float* __restrict__ Wo)
{
    const int idx = blockIdx.x * 256 + threadIdx.x;     // 0..131071
    const int r = idx >> 7, p = idx & 127;
    const float* W = (r < 256) ? Wq : ((r < 512) ? Wk : ((r < 768) ? Wv : Wo));
    const float2 w = *reinterpret_cast<const float2*>(&W[(size_t)(r & 255) * 256 + 2 * p]);
    uint32_t lo; const uint32_t hi = bfsplit2(w.x, w.y, lo);
    g_wh[idx] = hi; g_wl[idx] = lo;
}

// ---------------------------------------------------------------------------
// K0b: GN + bf16 split of x, once, token-major. 128 tokens per block.
// ---------------------------------------------------------------------------
__global__ void prep_x_kernel(const float* __restrict__ x,
                              const float* __restrict__ gnw, const float* __restrict__ gnb)
{
    __shared__ uint32_t Sh[128][17], Sl[128][17];
    const int tid = threadIdx.x;
    const int m0 = blockIdx.x * 128;

    for (int slab = 0; slab < 8; slab++) {
        __syncthreads();
        for (int i = tid; i < 2048; i += 256) {
            const int tok = i & 127, p = i >> 7;        // p 0..15
            const int c = slab * 32 + 2 * p;
            int bb, pix; tok2pix(m0 + tok, bb, pix);
            const size_t base = (size_t)bb * CH * IMG * IMG + pix;
            const float v0 = x[base + (size_t)c * (IMG * IMG)];
            const float v1 = x[base + (size_t)(c + 1) * (IMG * IMG)];
            const float mn = g_mean[bb * 32 + (c >> 3)];
            const float rs = g_rstd[bb * 32 + (c >> 3)];
            const float a = (v0 - mn) * rs * gnw[c]     + gnb[c];
            const float d = (v1 - mn) * rs * gnw[c + 1] + gnb[c + 1];
            uint32_t lo; const uint32_t hi = bfsplit2(a, d, lo);
            Sh[tok][p] = hi; Sl[tok][p] = lo;
        }
        __syncthreads();
        for (int i = tid; i < 2048; i += 256) {
            const int tok = i >> 4, p = i & 15;
            g_xh[(size_t)(m0 + tok) * 128 + slab * 16 + p] = Sh[tok][p];
            g_xl[(size_t)(m0 + tok) * 128 + slab * 16 + p] = Sl[tok][p];
        }
    }
}

// ---------------------------------------------------------------------------
// Shared GEMM mainloop (R13 known-good): C[128,128] += A[128,256]*B[128,256]^T,
// 3-term split-bf16. Single-stage cp.async fills (K chunk 64), ldmatrix frags,
// warp tile 32m x 64n, 64KB smem, 2 CTAs/SM.
// ---------------------------------------------------------------------------
#define SA_H 0
#define SA_L 16384
#define SB_H 32768
#define SB_L 49152
#define GM_SMEM 65536

__device__ __forceinline__ void gemm_mainloop128(
    uint32_t sbase,
    const uint32_t* __restrict__ Ah_g, const uint32_t* __restrict__ Al_g,
    const uint32_t* __restrict__ Bh_g, const uint32_t* __restrict__ Bl_g,
    float acc[2][8][4])
{
    const int tid = threadIdx.x, wid = tid >> 5, lane = tid & 31;
    const int wm = (wid & 3) * 32, wn = (wid >> 2) * 64;
    const int lrow = lane & 7, seg = lane >> 3;
    const int arow = wm + (seg & 1) * 8 + lrow;          // + mi*16
    const int brow = wn + (seg >> 1) * 8 + lrow;         // + half*32 + jj*16
    const int agc = seg >> 1;                            // + 2ks
    const int bgc = seg & 1;

    for (int kc = 0; kc < 4; kc++) {
        __syncthreads();
        #pragma unroll
        for (int i = tid; i < 1024; i += 256) {
            const int r = i >> 3, gc = i & 7;
            const size_t gs = (size_t)r * 128 + kc * 32 + gc * 4;
            const uint32_t so = r * 128 + ((gc ^ (r & 7)) << 4);
            cpa16(sbase + SA_H + so, Ah_g + gs);
            cpa16(sbase + SA_L + so, Al_g + gs);
            cpa16(sbase + SB_H + so, Bh_g + gs);
            cpa16(sbase + SB_L + so, Bl_g + gs);
        }
        asm volatile("cp.async.commit_group;");
        asm volatile("cp.async.wait_group 0;" ::: "memory");
        __syncthreads();
        #pragma unroll
        for (int ks = 0; ks < 4; ks++) {
            const int gA = 2 * ks + agc;
            const int gB = 2 * ks + bgc;
            uint4 ah[2], al[2];
            #pragma unroll
            for (int mi = 0; mi < 2; mi++) {
                const int r = arow + mi * 16;
                const uint32_t ad = sbase + SA_H + r * 128 + ((gA ^ (r & 7)) << 4);
                ldmx4(ah[mi], ad);
                ldmx4(al[mi], ad + (SA_L - SA_H));
            }
            #pragma unroll
            for (int half = 0; half < 2; half++) {
                uint4 bh[2], bl[2];
                #pragma unroll
                for (int jj = 0; jj < 2; jj++) {
                    const int r = brow + half * 32 + jj * 16;
                    const uint32_t bd = sbase + SB_H + r * 128 + ((gB ^ (r & 7)) << 4);
                    ldmx4(bh[jj], bd);
                    ldmx4(bl[jj], bd + (SB_L - SB_H));
                }
                #pragma unroll
                for (int jj = 0; jj < 2; jj++) {
                    const int n0 = half * 4 + 2 * jj;
                    #pragma unroll
                    for (int mi = 0; mi < 2; mi++) {
                        mma_bf16(acc[mi][n0],     ah[mi], bh[jj].x, bh[jj].y);
                        mma_bf16(acc[mi][n0],     al[mi], bh[jj].x, bh[jj].y);
                        mma_bf16(acc[mi][n0],     ah[mi], bl[jj].x, bl[jj].y);
                        mma_bf16(acc[mi][n0 + 1], ah[mi], bh[jj].z, bh[jj].w);
                        mma_bf16(acc[mi][n0 + 1], al[mi], bh[jj].z, bh[jj].w);
                        mma_bf16(acc[mi][n0 + 1], ah[mi], bl[jj].z, bl[jj].w);
                    }
                }
            }
        }
    }
}

// ---------------------------------------------------------------------------
// K2: QKV projection. grid (6, NTOK/128). nb 0-1: Q, 2-3: K, 4-5: V.
// ---------------------------------------------------------------------------
__global__ void __launch_bounds__(256, 2)
qkv_gemm_kernel(const float* __restrict__ scale)
{
    extern __shared__ char smc[];
    const uint32_t sbase = s2u(smc);
    const int tid = threadIdx.x, wid = tid >> 5, lane = tid & 31;
    const int nb = blockIdx.x;
    const int m0 = blockIdx.y * 128;

    float acc[2][8][4] = {};
    gemm_mainloop128(sbase,
                     g_xh + (size_t)m0 * 128, g_xl + (size_t)m0 * 128,
                     g_wh + (size_t)(nb * 128) * 128, g_wl + (size_t)(nb * 128) * 128,
                     acc);

    const int wm = (wid & 3) * 32, wn = (wid >> 2) * 64;
    const int g = lane >> 2, tg = lane & 3;

    if (nb < 4) {
        const bool isQ = nb < 2;
        const float mul = isQ ? scale[0] : 1.0f;
        const int pbase = (isQ ? 0 : 128) + (nb & 1) * 64 + wn / 2;
        #pragma unroll
        for (int mi = 0; mi < 2; mi++)
            #pragma unroll
            for (int half = 0; half < 2; half++) {
                const int row = m0 + wm + mi * 16 + g + half * 8;
                uint32_t* dh = &g_qkh[(size_t)row * 256 + pbase];
                uint32_t* dl = &g_qkl[(size_t)row * 256 + pbase];
                #pragma unroll
                for (int nj = 0; nj < 8; nj++) {
                    const float d0 = acc[mi][nj][half * 2]     * mul;
                    const float d1 = acc[mi][nj][half * 2 + 1] * mul;
                    uint32_t lo; const uint32_t hi = bfsplit2(d0, d1, lo);
                    dh[nj * 4 + tg] = hi;
                    dl[nj * 4 + tg] = lo;
                }
            }
    } else {
        const int cbase = (nb & 1) * 128 + wn;
        #pragma unroll
        for (int mi = 0; mi < 2; mi++)
            #pragma unroll
            for (int half = 0; half < 2; half++) {
                const int row = m0 + wm + mi * 16 + g + half * 8;
                #pragma unroll
                for (int nj = 0; nj < 8; nj++) {
                    const int c = cbase + nj * 8 + 2 * tg;
                    *reinterpret_cast<float2*>(&g_v[(size_t)row * 256 + c]) = make_float2(
                        __uint_as_float(f2tf(acc[mi][nj][half * 2])),
                        __uint_as_float(f2tf(acc[mi][nj][half * 2 + 1])));
                }
            }
    }
}

// ---------------------------------------------------------------------------
// K3: per-window attention (R13 structure, 4 CTAs/SM). Changes vs R13:
//  - Q/K fills via cp.async (pure copies)
//  - V stored ROW-MAJOR [token][40 floats] via cp.async (no transpose);
//    S.V B-fragment reads V[(k)*40 + n]: lane addr mod 32 = 8*tg+g -> conflict
//    free. Same values bit-for-bit -> rel_err must stay 1.6748e-4.
// smem: QH 0 | QL 5120 | KH 10240 | KL 15360 | Vrm 20480 (64x160B)
//       | SS 30720 (64x68 f32) -> total 48128 B.
// ---------------------------------------------------------------------------
#define AQ_H 0
#define AQ_L 5120
#define AK_H 10240
#define AK_L 15360
#define AVT  20480
#define ASS  30720
#define AT_SMEM 48128

__global__ void __launch_bounds__(256)
attn_kernel(const float* __restrict__ pos)
{
    extern __shared__ char smc[];
    const uint32_t sbase = s2u(smc);
    float* Vrm = reinterpret_cast<float*>(smc + AVT);  // [64 tok][40]
    float* SS  = reinterpret_cast<float*>(smc + ASS);  // [64][68]

    const int tid = threadIdx.x;
    const int wid = tid >> 5, lane = tid & 31;
    const int g = lane >> 2, tg = lane & 3;
    const int m0 = blockIdx.x * NT;

    const int mtile = wid >> 1;
    const int ms = mtile * 16;
    const int nq = (wid & 1) * 4;
    const int np = (wid & 1) * 2;
    const int lrow = lane & 7, seg = lane >> 3;

    for (int h = 0; h < NHEAD; h++) {
        __syncthreads();
        // ---- fills via cp.async: Q/K split pairs + V row-major ----
        for (int i = tid; i < 512; i += 256) {
            const int isK = i >> 8;
            const int r = (i >> 2) & 63, gc = i & 3;
            const size_t gs = (size_t)(m0 + r) * 256 + (isK ? 128 : 0) + h * 16 + gc * 4;
            const uint32_t so = (isK ? (uint32_t)AK_H : (uint32_t)AQ_H) + r * 80 + gc * 16;
            cpa16(sbase + so, g_qkh + gs);
            cpa16(sbase + so + 5120, g_qkl + gs);
        }
        for (int i = tid; i < 512; i += 256) {
            const int t = i >> 3, q = i & 7;
            cpa16(sbase + AVT + t * 160 + q * 16,
                  g_v + (size_t)(m0 + t) * 256 + h * 32 + q * 4);
        }
        asm volatile("cp.async.commit_group;");
        asm volatile("cp.async.wait_group 0;" ::: "memory");
        __syncthreads();

        // ---- S = Q K^T, 3-term bf16 via ldmatrix ----
        float sacc[4][4];
        #pragma unroll
        for (int j = 0; j < 4; j++)
            #pragma unroll
            for (int z = 0; z < 4; z++) sacc[j][z] = 0.f;

        #pragma unroll
        for (int ks = 0; ks < 2; ks++) {
            const int gA = 2 * ks + (seg >> 1);
            const int gB = 2 * ks + (seg & 1);
            const int qrow = ms + (seg & 1) * 8 + lrow;
            uint4 qh, ql;
            ldmx4(qh, sbase + AQ_H + qrow * 80 + gA * 16);
            ldmx4(ql, sbase + AQ_L + qrow * 80 + gA * 16);
            #pragma unroll
            for (int jj = 0; jj < 2; jj++) {
                const int krow = (nq + 2 * jj) * 8 + (seg >> 1) * 8 + lrow;
                uint4 kh, kl;
                ldmx4(kh, sbase + AK_H + krow * 80 + gB * 16);
                ldmx4(kl, sbase + AK_L + krow * 80 + gB * 16);
                mma_bf16(sacc[2 * jj],     qh, kh.x, kh.y);
                mma_bf16(sacc[2 * jj],     ql, kh.x, kh.y);
                mma_bf16(sacc[2 * jj],     qh, kl.x, kl.y);
                mma_bf16(sacc[2 * jj + 1], qh, kh.z, kh.w);
                mma_bf16(sacc[2 * jj + 1], ql, kh.z, kh.w);
                mma_bf16(sacc[2 * jj + 1], qh, kl.z, kl.w);
            }
        }
        // SS = sacc + pos (direct)
        #pragma unroll
        for (int j = 0; j < 4; j++) {
            const int c = (nq + j) * 8 + 2 * tg;
            const int row = ms + g;
            const float2 pv0 = *reinterpret_cast<const float2*>(
                &pos[h * 4096 + row * 64 + c]);
            *reinterpret_cast<float2*>(&SS[row * 68 + c]) =
                make_float2(sacc[j][0] + pv0.x, sacc[j][1] + pv0.y);
            const float2 pv1 = *reinterpret_cast<const float2*>(
                &pos[h * 4096 + (row + 8) * 64 + c]);
            *reinterpret_cast<float2*>(&SS[(row + 8) * 68 + c]) =
                make_float2(sacc[j][2] + pv1.x, sacc[j][3] + pv1.y);
        }
        __syncthreads();

        // ---- softmax (2 threads per row); store tf32-pre-rounded probs ----
        if (tid < 128) {
            const int row = tid >> 1, half = tid & 1;
            float* p = &SS[row * 68 + half * 32];
            float m = -1e30f;
            #pragma unroll 8
            for (int j = 0; j < 32; j++) m = fmaxf(m, p[j]);
            m = fmaxf(m, __shfl_xor_sync(0xFFFFFFFFu, m, 1));
            float s = 0.f;
            #pragma unroll 8
            for (int j = 0; j < 32; j++) { const float e = __expf(p[j] - m); p[j] = e; s += e; }
            s += __shfl_xor_sync(0xFFFFFFFFu, s, 1);
            const float inv = 1.f / s;
            #pragma unroll 8
            for (int j = 0; j < 32; j++)
                p[j] = __uint_as_float(f2tf(p[j] * inv));
        }
        __syncthreads();

        // ---- O = S @ V (tf32; V read from row-major pad-40 layout) ----
        float oacc[2][4];
        #pragma unroll
        for (int j = 0; j < 2; j++)
            #pragma unroll
            for (int z = 0; z < 4; z++) oacc[j][z] = 0.f;

        #pragma unroll
        for (int ks = 0; ks < 8; ks++) {
            const int kk = ks * 8;
            const float* Sp = &SS[(ms + g) * 68 + kk + tg];
            const uint32_t a0 = __float_as_uint(Sp[0]);
            const uint32_t a1 = __float_as_uint(Sp[8 * 68]);
            const uint32_t a2 = __float_as_uint(Sp[4]);
            const uint32_t a3 = __float_as_uint(Sp[8 * 68 + 4]);
            #pragma unroll
            for (int j = 0; j < 2; j++) {
                const float* Vp = &Vrm[(kk + tg) * 40 + (np + j) * 8 + g];
                mma_tf32(oacc[j], a0, a1, a2, a3,
                         __float_as_uint(Vp[0]), __float_as_uint(Vp[160]));
            }
        }
        #pragma unroll
        for (int j = 0; j < 2; j++) {
            const int pb = h * 16 + (np + j) * 4 + tg;
            #pragma unroll
            for (int half = 0; half < 2; half++) {
                const int row = ms + g + half * 8;
                uint32_t lo;
                const uint32_t hi = bfsplit2(oacc[j][half * 2], oacc[j][half * 2 + 1], lo);
                g_ath[(size_t)(m0 + row) * 128 + pb] = hi;
                g_atl[(size_t)(m0 + row) * 128 + pb] = lo;
            }
        }
    }
}

// ---------------------------------------------------------------------------
// K4: output projection (3-term bf16, 128x128 tile) + bias + residual.
// grid (2, NTOK/128).
// ---------------------------------------------------------------------------
__global__ void __launch_bounds__(256, 2)
outproj_gemm_kernel(const float* __restrict__ x, const float* __restrict__ bo,
                    float* __restrict__ out)
{
    extern __shared__ char smc[];
    const uint32_t sbase = s2u(smc);
    const int tid = threadIdx.x, wid = tid >> 5, lane = tid & 31;
    const int nb = blockIdx.x;           // 0..1
    const int m0 = blockIdx.y * 128;

    float acc[2][8][4] = {};
    gemm_mainloop128(sbase,
                     g_ath + (size_t)m0 * 128, g_atl + (size_t)m0 * 128,
                     g_wh + (size_t)(768 + nb * 128) * 128,
                     g_wl + (size_t)(768 + nb * 128) * 128,
                     acc);

    const int wm = (wid & 3) * 32, wn = (wid >> 2) * 64;
    const int g = lane >> 2, tg = lane & 3;
    const int n0 = nb * 128;
    #pragma unroll
    for (int mi = 0; mi < 2; mi++) {
        #pragma unroll
        for (int half = 0; half < 2; half++) {
            const int r = wm + mi * 16 + g + half * 8;
            int b, pix; tok2pix(m0 + r, b, pix);
            const size_t base = (size_t)b * CH * IMG * IMG + pix;
            #pragma unroll
            for (int nj = 0; nj < 8; nj++) {
                const int c0 = n0 + wn + nj * 8 + 2 * tg;
                const size_t a0 = base + (size_t)c0 * (IMG * IMG);
                const size_t a1 = a0 + (IMG * IMG);
                out[a0] = acc[mi][nj][half * 2 + 0] + bo[c0]     + x[a0];
                out[a1] = acc[mi][nj][half * 2 + 1] + bo[c0 + 1] + x[a1];
            }
        }
    }
}

// ---------------------------------------------------------------------------
extern "C" void kernel_launch(void* const* d_in, const int* in_sizes, int n_in,
                              void* d_out, int out_size)
{
    const float* x    = (const float*)d_in[0];
    const float* gnw  = (const float*)d_in[1];
    const float* gnb  = (const float*)d_in[2];
    const float* Wq   = (const float*)d_in[3];
    const float* Wk   = (const float*)d_in[4];
    const float* Wv   = (const float*)d_in[5];
    const float* Wo   = (const float*)d_in[6];
    const float* bo   = (const float*)d_in[7];
    const float* pos  = (const float*)d_in[8];
    const float* scl  = (const float*)d_in[9];
    float* out = (float*)d_out;

    cudaFuncSetAttribute(qkv_gemm_kernel,     cudaFuncAttributeMaxDynamicSharedMemorySize, GM_SMEM);
    cudaFuncSetAttribute(outproj_gemm_kernel, cudaFuncAttributeMaxDynamicSharedMemorySize, GM_SMEM);
    cudaFuncSetAttribute(attn_kernel,         cudaFuncAttributeMaxDynamicSharedMemorySize, AT_SMEM);

    gn_stats_kernel<<<BATCH * 32, 512>>>(x);
    prep_w_kernel<<<512, 256>>>(Wq, Wk, Wv, Wo);
    prep_x_kernel<<<NTOK / 128, 256>>>(x, gnw, gnb);
    qkv_gemm_kernel<<<dim3(6, NTOK / 128), 256, GM_SMEM>>>(scl);
    attn_kernel<<<NTOK / NT, 256, AT_SMEM>>>(pos);
    outproj_gemm_kernel<<<dim3(2, NTOK / 128), 256, GM_SMEM>>>(x, bo, out);
}

// round 17
// speedup vs baseline: 1.2268x; 1.0430x over previous
#include <cuda_runtime.h>
#include <cuda_bf16.h>
#include <cuda_fp16.h>
#include <cstdint>

#define BATCH  4
#define CH     256
#define IMG    256
#define WSZ    8
#define NT     64
#define NHEAD  8
#define GN_EPS 1e-5f
#define NTOK   (BATCH * IMG * IMG)          // 262144

// ---- device-global scratch (allocation is banned) ----
__device__ float    g_mean[BATCH * 32];
__device__ float    g_rstd[BATCH * 32];
__device__ uint32_t g_xh[(size_t)NTOK * 128];   // GN(x) bf16x2 hi, [token][128]
__device__ uint32_t g_xl[(size_t)NTOK * 128];   // lo residual
__device__ uint32_t g_wh[1024 * 128];           // Wq|Wk|Wv bf16 splits; Wo fp16 splits
__device__ uint32_t g_wl[1024 * 128];
__device__ uint32_t g_qkh[(size_t)NTOK * 256];  // [token][Q 128 pairs | K 128 pairs] hi
__device__ uint32_t g_qkl[(size_t)NTOK * 256];
__device__ float    g_v  [(size_t)NTOK * 256];  // V, tf32-rounded fp32
__device__ uint32_t g_ath[(size_t)NTOK * 128];  // attention out, fp16 split
__device__ uint32_t g_atl[(size_t)NTOK * 128];

// ---------------------------------------------------------------------------
// helpers
// ---------------------------------------------------------------------------
__device__ __forceinline__ uint32_t f2tf(float f) {
    uint32_t u; asm("cvt.rna.tf32.f32 %0, %1;" : "=r"(u) : "f"(f)); return u;
}
__device__ __forceinline__ void mma_tf32(float d[4],
    uint32_t a0, uint32_t a1, uint32_t a2, uint32_t a3,
    uint32_t b0, uint32_t b1)
{
    asm("mma.sync.aligned.m16n8k8.row.col.f32.tf32.tf32.f32 "
        "{%0,%1,%2,%3},{%4,%5,%6,%7},{%8,%9},{%0,%1,%2,%3};"
        : "+f"(d[0]), "+f"(d[1]), "+f"(d[2]), "+f"(d[3])
        : "r"(a0), "r"(a1), "r"(a2), "r"(a3), "r"(b0), "r"(b1));
}
__device__ __forceinline__ void mma_bf16(float d[4], uint4 a, uint32_t b0, uint32_t b1)
{
    asm("mma.sync.aligned.m16n8k16.row.col.f32.bf16.bf16.f32 "
        "{%0,%1,%2,%3},{%4,%5,%6,%7},{%8,%9},{%0,%1,%2,%3};"
        : "+f"(d[0]), "+f"(d[1]), "+f"(d[2]), "+f"(d[3])
        : "r"(a.x), "r"(a.y), "r"(a.z), "r"(a.w), "r"(b0), "r"(b1));
}
__device__ __forceinline__ void mma_f16(float d[4], uint4 a, uint32_t b0, uint32_t b1)
{
    asm("mma.sync.aligned.m16n8k16.row.col.f32.f16.f16.f32 "
        "{%0,%1,%2,%3},{%4,%5,%6,%7},{%8,%9},{%0,%1,%2,%3};"
        : "+f"(d[0]), "+f"(d[1]), "+f"(d[2]), "+f"(d[3])
        : "r"(a.x), "r"(a.y), "r"(a.z), "r"(a.w), "r"(b0), "r"(b1));
}
__device__ __forceinline__ void ldmx4(uint4& d, uint32_t addr) {
    asm volatile("ldmatrix.sync.aligned.m8n8.x4.shared.b16 {%0,%1,%2,%3}, [%4];"
        : "=r"(d.x), "=r"(d.y), "=r"(d.z), "=r"(d.w) : "r"(addr));
}
__device__ __forceinline__ uint32_t s2u(const void* p) {
    uint32_t a;
    asm("{ .reg .u64 t; cvta.to.shared.u64 t, %1; cvt.u32.u64 %0, t; }" : "=r"(a) : "l"(p));
    return a;
}
__device__ __forceinline__ void cpa16(uint32_t saddr, const void* gptr) {
    asm volatile("cp.async.cg.shared.global [%0], [%1], 16;" :: "r"(saddr), "l"(gptr));
}
__device__ __forceinline__ void tok2pix(int m, int& b, int& pix) {
    b = m >> 16;
    const int win = (m >> 6) & 1023;
    const int t   = m & 63;
    pix = ((win >> 5) * WSZ + (t >> 3)) * IMG + (win & 31) * WSZ + (t & 7);
}
__device__ __forceinline__ uint32_t bfsplit2(float a, float b, uint32_t& lo) {
    __nv_bfloat16 ah = __float2bfloat16(a);
    __nv_bfloat16 bh = __float2bfloat16(b);
    __nv_bfloat16 al = __float2bfloat16(a - __bfloat162float(ah));
    __nv_bfloat16 bl = __float2bfloat16(b - __bfloat162float(bh));
    lo = (uint32_t)__bfloat16_as_ushort(al) | ((uint32_t)__bfloat16_as_ushort(bl) << 16);
    return (uint32_t)__bfloat16_as_ushort(ah) | ((uint32_t)__bfloat16_as_ushort(bh) << 16);
}
__device__ __forceinline__ uint32_t hsplit2(float a, float b, uint32_t& lo) {
    __half ah = __float2half_rn(a);
    __half bh = __float2half_rn(b);
    __half al = __float2half_rn(a - __half2float(ah));
    __half bl = __float2half_rn(b - __half2float(bh));
    lo = (uint32_t)__half_as_ushort(al) | ((uint32_t)__half_as_ushort(bl) << 16);
    return (uint32_t)__half_as_ushort(ah) | ((uint32_t)__half_as_ushort(bh) << 16);
}

// ---------------------------------------------------------------------------
// K1: GroupNorm statistics
// ---------------------------------------------------------------------------
__global__ void gn_stats_kernel(const float* __restrict__ x)
{
    const int bg = blockIdx.x;
    const float4* p = reinterpret_cast<const float4*>(x + (size_t)bg * 8 * IMG * IMG);
    const int n4 = (8 * IMG * IMG) / 4;

    float s = 0.f, sq = 0.f;
    for (int i = threadIdx.x; i < n4; i += blockDim.x) {
        float4 v = p[i];
        s  += v.x + v.y + v.z + v.w;
        sq += v.x * v.x + v.y * v.y + v.z * v.z + v.w * v.w;
    }
    for (int o = 16; o; o >>= 1) {
        s  += __shfl_down_sync(0xFFFFFFFFu, s,  o);
        sq += __shfl_down_sync(0xFFFFFFFFu, sq, o);
    }
    __shared__ float ss[32], ssq[32];
    const int w = threadIdx.x >> 5, l = threadIdx.x & 31;
    if (l == 0) { ss[w] = s; ssq[w] = sq; }
    __syncthreads();
    if (w == 0) {
        const int nw = blockDim.x >> 5;
        s  = (l < nw) ? ss[l]  : 0.f;
        sq = (l < nw) ? ssq[l] : 0.f;
        for (int o = 16; o; o >>= 1) {
            s  += __shfl_down_sync(0xFFFFFFFFu, s,  o);
            sq += __shfl_down_sync(0xFFFFFFFFu, sq, o);
        }
        if (l == 0) {
            const float invN = 1.f / (float)(8 * IMG * IMG);
            const float m   = s * invN;
            const float var = sq * invN - m * m;
            g_mean[bg] = m;
            g_rstd[bg] = rsqrtf(var + GN_EPS);
        }
    }
}

// ---------------------------------------------------------------------------
// K0a: split all weights once. Wq|Wk|Wv (rows 0..767): bf16 splits.
// Wo (rows 768..1023): fp16 splits (for 2-term fp16 outproj).
// ---------------------------------------------------------------------------
__global__ void prep_w_kernel(const float* __restrict__ Wq, const float* __restrict__ Wk,
                              const float* __restrict__ Wv, const float* __restrict__ Wo)
{
    const int idx = blockIdx.x * 256 + threadIdx.x;     // 0..131071
    const int r = idx >> 7, p = idx & 127;
    const float* W = (r < 256) ? Wq : ((r < 512) ? Wk : ((r < 768) ? Wv : Wo));
    const float2 w = *reinterpret_cast<const float2*>(&W[(size_t)(r & 255) * 256 + 2 * p]);
    uint32_t lo, hi;
    if (r < 768) hi = bfsplit2(w.x, w.y, lo);
    else         hi = hsplit2(w.x, w.y, lo);
    g_wh[idx] = hi; g_wl[idx] = lo;
}

// ---------------------------------------------------------------------------
// K0b: GN + bf16 split of x. Lane mapping reads 16 consecutive pixels across
// the adjacent window pair (64B runs) for 2x sector efficiency vs R16.
// Same values to the same smem cells -> output bit-identical.
// ---------------------------------------------------------------------------
__global__ void prep_x_kernel(const float* __restrict__ x,
                              const float* __restrict__ gnw, const float* __restrict__ gnb)
{
    __shared__ uint32_t Sh[128][17], Sl[128][17];
    const int tid = threadIdx.x;
    const int m0 = blockIdx.x * 128;

    int bb, pix0; tok2pix(m0, bb, pix0);          // token 0 of window A
    const size_t base0 = (size_t)bb * CH * IMG * IMG + pix0;

    for (int slab = 0; slab < 8; slab++) {
        __syncthreads();
        for (int i = tid; i < 2048; i += 256) {
            const int px16 = i & 15;               // 16 consecutive x-pixels
            const int row  = (i >> 4) & 7;         // window row 0..7
            const int p    = i >> 7;               // channel pair 0..15
            const int c    = slab * 32 + 2 * p;
            const int tok  = ((px16 >> 3) << 6) + row * 8 + (px16 & 7);
            const size_t base = base0 + row * IMG + px16;
            const float v0 = x[base + (size_t)c * (IMG * IMG)];
            const float v1 = x[base + (size_t)(c + 1) * (IMG * IMG)];
            const float mn = g_mean[bb * 32 + (c >> 3)];
            const float rs = g_rstd[bb * 32 + (c >> 3)];
            const float a = (v0 - mn) * rs * gnw[c]     + gnb[c];
            const float d = (v1 - mn) * rs * gnw[c + 1] + gnb[c + 1];
            uint32_t lo; const uint32_t hi = bfsplit2(a, d, lo);
            Sh[tok][p] = hi; Sl[tok][p] = lo;
        }
        __syncthreads();
        for (int i = tid; i < 2048; i += 256) {
            const int tok = i >> 4, p = i & 15;
            g_xh[(size_t)(m0 + tok) * 128 + slab * 16 + p] = Sh[tok][p];
            g_xl[(size_t)(m0 + tok) * 128 + slab * 16 + p] = Sl[tok][p];
        }
    }
}

// ---------------------------------------------------------------------------
// Shared GEMM mainloop (R13/R16 known-good): 3-term split-bf16.
// ---------------------------------------------------------------------------
#define SA_H 0
#define SA_L 16384
#define SB_H 32768
#define SB_L 49152
#define GM_SMEM 65536

__device__ __forceinline__ void gemm_mainloop128(
    uint32_t sbase,
    const uint32_t* __restrict__ Ah_g, const uint32_t* __restrict__ Al_g,
    const uint32_t* __restrict__ Bh_g, const uint32_t* __restrict__ Bl_g,
    float acc[2][8][4])
{
    const int tid = threadIdx.x, wid = tid >> 5, lane = tid & 31;
    const int wm = (wid & 3) * 32, wn = (wid >> 2) * 64;
    const int lrow = lane & 7, seg = lane >> 3;
    const int arow = wm + (seg & 1) * 8 + lrow;
    const int brow = wn + (seg >> 1) * 8 + lrow;
    const int agc = seg >> 1;
    const int bgc = seg & 1;

    for (int kc = 0; kc < 4; kc++) {
        __syncthreads();
        #pragma unroll
        for (int i = tid; i < 1024; i += 256) {
            const int r = i >> 3, gc = i & 7;
            const size_t gs = (size_t)r * 128 + kc * 32 + gc * 4;
            const uint32_t so = r * 128 + ((gc ^ (r & 7)) << 4);
            cpa16(sbase + SA_H + so, Ah_g + gs);
            cpa16(sbase + SA_L + so, Al_g + gs);
            cpa16(sbase + SB_H + so, Bh_g + gs);
            cpa16(sbase + SB_L + so, Bl_g + gs);
        }
        asm volatile("cp.async.commit_group;");
        asm volatile("cp.async.wait_group 0;" ::: "memory");
        __syncthreads();
        #pragma unroll
        for (int ks = 0; ks < 4; ks++) {
            const int gA = 2 * ks + agc;
            const int gB = 2 * ks + bgc;
            uint4 ah[2], al[2];
            #pragma unroll
            for (int mi = 0; mi < 2; mi++) {
                const int r = arow + mi * 16;
                const uint32_t ad = sbase + SA_H + r * 128 + ((gA ^ (r & 7)) << 4);
                ldmx4(ah[mi], ad);
                ldmx4(al[mi], ad + (SA_L - SA_H));
            }
            #pragma unroll
            for (int half = 0; half < 2; half++) {
                uint4 bh[2], bl[2];
                #pragma unroll
                for (int jj = 0; jj < 2; jj++) {
                    const int r = brow + half * 32 + jj * 16;
                    const uint32_t bd = sbase + SB_H + r * 128 + ((gB ^ (r & 7)) << 4);
                    ldmx4(bh[jj], bd);
                    ldmx4(bl[jj], bd + (SB_L - SB_H));
                }
                #pragma unroll
                for (int jj = 0; jj < 2; jj++) {
                    const int n0 = half * 4 + 2 * jj;
                    #pragma unroll
                    for (int mi = 0; mi < 2; mi++) {
                        mma_bf16(acc[mi][n0],     ah[mi], bh[jj].x, bh[jj].y);
                        mma_bf16(acc[mi][n0],     al[mi], bh[jj].x, bh[jj].y);
                        mma_bf16(acc[mi][n0],     ah[mi], bl[jj].x, bl[jj].y);
                        mma_bf16(acc[mi][n0 + 1], ah[mi], bh[jj].z, bh[jj].w);
                        mma_bf16(acc[mi][n0 + 1], al[mi], bh[jj].z, bh[jj].w);
                        mma_bf16(acc[mi][n0 + 1], ah[mi], bl[jj].z, bl[jj].w);
                    }
                }
            }
        }
    }
}

// ---------------------------------------------------------------------------
// 2-term fp16 mainloop for outproj: A = ah+al (fp16 pair), B = bh only.
// B-lo fills and ah*bl mma removed. fp16 11-bit precision == tf32 class.
// ---------------------------------------------------------------------------
__device__ __forceinline__ void gemm_mainloop128_f16_2t(
    uint32_t sbase,
    const uint32_t* __restrict__ Ah_g, const uint32_t* __restrict__ Al_g,
    const uint32_t* __restrict__ Bh_g,
    float acc[2][8][4])
{
    const int tid = threadIdx.x, wid = tid >> 5, lane = tid & 31;
    const int wm = (wid & 3) * 32, wn = (wid >> 2) * 64;
    const int lrow = lane & 7, seg = lane >> 3;
    const int arow = wm + (seg & 1) * 8 + lrow;
    const int brow = wn + (seg >> 1) * 8 + lrow;
    const int agc = seg >> 1;
    const int bgc = seg & 1;

    for (int kc = 0; kc < 4; kc++) {
        __syncthreads();
        #pragma unroll
        for (int i = tid; i < 1024; i += 256) {
            const int r = i >> 3, gc = i & 7;
            const size_t gs = (size_t)r * 128 + kc * 32 + gc * 4;
            const uint32_t so = r * 128 + ((gc ^ (r & 7)) << 4);
            cpa16(sbase + SA_H + so, Ah_g + gs);
            cpa16(sbase + SA_L + so, Al_g + gs);
            cpa16(sbase + SB_H + so, Bh_g + gs);
        }
        asm volatile("cp.async.commit_group;");
        asm volatile("cp.async.wait_group 0;" ::: "memory");
        __syncthreads();
        #pragma unroll
        for (int ks = 0; ks < 4; ks++) {
            const int gA = 2 * ks + agc;
            const int gB = 2 * ks + bgc;
            uint4 ah[2], al[2];
            #pragma unroll
            for (int mi = 0; mi < 2; mi++) {
                const int r = arow + mi * 16;
                const uint32_t ad = sbase + SA_H + r * 128 + ((gA ^ (r & 7)) << 4);
                ldmx4(ah[mi], ad);
                ldmx4(al[mi], ad + (SA_L - SA_H));
            }
            #pragma unroll
            for (int half = 0; half < 2; half++) {
                uint4 bh[2];
                #pragma unroll
                for (int jj = 0; jj < 2; jj++) {
                    const int r = brow + half * 32 + jj * 16;
                    ldmx4(bh[jj], sbase + SB_H + r * 128 + ((gB ^ (r & 7)) << 4));
                }
                #pragma unroll
                for (int jj = 0; jj < 2; jj++) {
                    const int n0 = half * 4 + 2 * jj;
                    #pragma unroll
                    for (int mi = 0; mi < 2; mi++) {
                        mma_f16(acc[mi][n0],     ah[mi], bh[jj].x, bh[jj].y);
                        mma_f16(acc[mi][n0],     al[mi], bh[jj].x, bh[jj].y);
                        mma_f16(acc[mi][n0 + 1], ah[mi], bh[jj].z, bh[jj].w);
                        mma_f16(acc[mi][n0 + 1], al[mi], bh[jj].z, bh[jj].w);
                    }
                }
            }
        }
    }
}

// ---------------------------------------------------------------------------
// K2: QKV projection. grid (6, NTOK/128). nb 0-1: Q, 2-3: K, 4-5: V.
// ---------------------------------------------------------------------------
__global__ void __launch_bounds__(256, 2)
qkv_gemm_kernel(const float* __restrict__ scale)
{
    extern __shared__ char smc[];
    const uint32_t sbase = s2u(smc);
    const int tid = threadIdx.x, wid = tid >> 5, lane = tid & 31;
    const int nb = blockIdx.x;
    const int m0 = blockIdx.y * 128;

    float acc[2][8][4] = {};
    gemm_mainloop128(sbase,
                     g_xh + (size_t)m0 * 128, g_xl + (size_t)m0 * 128,
                     g_wh + (size_t)(nb * 128) * 128, g_wl + (size_t)(nb * 128) * 128,
                     acc);

    const int wm = (wid & 3) * 32, wn = (wid >> 2) * 64;
    const int g = lane >> 2, tg = lane & 3;

    if (nb < 4) {
        const bool isQ = nb < 2;
        const float mul = isQ ? scale[0] : 1.0f;
        const int pbase = (isQ ? 0 : 128) + (nb & 1) * 64 + wn / 2;
        #pragma unroll
        for (int mi = 0; mi < 2; mi++)
            #pragma unroll
            for (int half = 0; half < 2; half++) {
                const int row = m0 + wm + mi * 16 + g + half * 8;
                uint32_t* dh = &g_qkh[(size_t)row * 256 + pbase];
                uint32_t* dl = &g_qkl[(size_t)row * 256 + pbase];
                #pragma unroll
                for (int nj = 0; nj < 8; nj++) {
                    const float d0 = acc[mi][nj][half * 2]     * mul;
                    const float d1 = acc[mi][nj][half * 2 + 1] * mul;
                    uint32_t lo; const uint32_t hi = bfsplit2(d0, d1, lo);
                    dh[nj * 4 + tg] = hi;
                    dl[nj * 4 + tg] = lo;
                }
            }
    } else {
        const int cbase = (nb & 1) * 128 + wn;
        #pragma unroll
        for (int mi = 0; mi < 2; mi++)
            #pragma unroll
            for (int half = 0; half < 2; half++) {
                const int row = m0 + wm + mi * 16 + g + half * 8;
                #pragma unroll
                for (int nj = 0; nj < 8; nj++) {
                    const int c = cbase + nj * 8 + 2 * tg;
                    *reinterpret_cast<float2*>(&g_v[(size_t)row * 256 + c]) = make_float2(
                        __uint_as_float(f2tf(acc[mi][nj][half * 2])),
                        __uint_as_float(f2tf(acc[mi][nj][half * 2 + 1])));
                }
            }
    }
}

// ---------------------------------------------------------------------------
// K3: per-window attention (R16 structure; epilogue stores fp16 splits).
// ---------------------------------------------------------------------------
#define AQ_H 0
#define AQ_L 5120
#define AK_H 10240
#define AK_L 15360
#define AVT  20480
#define ASS  30720
#define AT_SMEM 48128

__global__ void __launch_bounds__(256)
attn_kernel(const float* __restrict__ pos)
{
    extern __shared__ char smc[];
    const uint32_t sbase = s2u(smc);
    float* Vrm = reinterpret_cast<float*>(smc + AVT);  // [64 tok][40]
    float* SS  = reinterpret_cast<float*>(smc + ASS);  // [64][68]

    const int tid = threadIdx.x;
    const int wid = tid >> 5, lane = tid & 31;
    const int g = lane >> 2, tg = lane & 3;
    const int m0 = blockIdx.x * NT;

    const int mtile = wid >> 1;
    const int ms = mtile * 16;
    const int nq = (wid & 1) * 4;
    const int np = (wid & 1) * 2;
    const int lrow = lane & 7, seg = lane >> 3;

    for (int h = 0; h < NHEAD; h++) {
        __syncthreads();
        for (int i = tid; i < 512; i += 256) {
            const int isK = i >> 8;
            const int r = (i >> 2) & 63, gc = i & 3;
            const size_t gs = (size_t)(m0 + r) * 256 + (isK ? 128 : 0) + h * 16 + gc * 4;
            const uint32_t so = (isK ? (uint32_t)AK_H : (uint32_t)AQ_H) + r * 80 + gc * 16;
            cpa16(sbase + so, g_qkh + gs);
            cpa16(sbase + so + 5120, g_qkl + gs);
        }
        for (int i = tid; i < 512; i += 256) {
            const int t = i >> 3, q = i & 7;
            cpa16(sbase + AVT + t * 160 + q * 16,
                  g_v + (size_t)(m0 + t) * 256 + h * 32 + q * 4);
        }
        asm volatile("cp.async.commit_group;");
        asm volatile("cp.async.wait_group 0;" ::: "memory");
        __syncthreads();

        float sacc[4][4];
        #pragma unroll
        for (int j = 0; j < 4; j++)
            #pragma unroll
            for (int z = 0; z < 4; z++) sacc[j][z] = 0.f;

        #pragma unroll
        for (int ks = 0; ks < 2; ks++) {
            const int gA = 2 * ks + (seg >> 1);
            const int gB = 2 * ks + (seg & 1);
            const int qrow = ms + (seg & 1) * 8 + lrow;
            uint4 qh, ql;
            ldmx4(qh, sbase + AQ_H + qrow * 80 + gA * 16);
            ldmx4(ql, sbase + AQ_L + qrow * 80 + gA * 16);
            #pragma unroll
            for (int jj = 0; jj < 2; jj++) {
                const int krow = (nq + 2 * jj) * 8 + (seg >> 1) * 8 + lrow;
                uint4 kh, kl;
                ldmx4(kh, sbase + AK_H + krow * 80 + gB * 16);
                ldmx4(kl, sbase + AK_L + krow * 80 + gB * 16);
                mma_bf16(sacc[2 * jj],     qh, kh.x, kh.y);
                mma_bf16(sacc[2 * jj],     ql, kh.x, kh.y);
                mma_bf16(sacc[2 * jj],     qh, kl.x, kl.y);
                mma_bf16(sacc[2 * jj + 1], qh, kh.z, kh.w);
                mma_bf16(sacc[2 * jj + 1], ql, kh.z, kh.w);
                mma_bf16(sacc[2 * jj + 1], qh, kl.z, kl.w);
            }
        }
        #pragma unroll
        for (int j = 0; j < 4; j++) {
            const int c = (nq + j) * 8 + 2 * tg;
            const int row = ms + g;
            const float2 pv0 = *reinterpret_cast<const float2*>(
                &pos[h * 4096 + row * 64 + c]);
            *reinterpret_cast<float2*>(&SS[row * 68 + c]) =
                make_float2(sacc[j][0] + pv0.x, sacc[j][1] + pv0.y);
            const float2 pv1 = *reinterpret_cast<const float2*>(
                &pos[h * 4096 + (row + 8) * 64 + c]);
            *reinterpret_cast<float2*>(&SS[(row + 8) * 68 + c]) =
                make_float2(sacc[j][2] + pv1.x, sacc[j][3] + pv1.y);
        }
        __syncthreads();

        if (tid < 128) {
            const int row = tid >> 1, half = tid & 1;
            float* p = &SS[row * 68 + half * 32];
            float m = -1e30f;
            #pragma unroll 8
            for (int j = 0; j < 32; j++) m = fmaxf(m, p[j]);
            m = fmaxf(m, __shfl_xor_sync(0xFFFFFFFFu, m, 1));
            float s = 0.f;
            #pragma unroll 8
            for (int j = 0; j < 32; j++) { const float e = __expf(p[j] - m); p[j] = e; s += e; }
            s += __shfl_xor_sync(0xFFFFFFFFu, s, 1);
            const float inv = 1.f / s;
            #pragma unroll 8
            for (int j = 0; j < 32; j++)
                p[j] = __uint_as_float(f2tf(p[j] * inv));
        }
        __syncthreads();

        float oacc[2][4];
        #pragma unroll
        for (int j = 0; j < 2; j++)
            #pragma unroll
            for (int z = 0; z < 4; z++) oacc[j][z] = 0.f;

        #pragma unroll
        for (int ks = 0; ks < 8; ks++) {
            const int kk = ks * 8;
            const float* Sp = &SS[(ms + g) * 68 + kk + tg];
            const uint32_t a0 = __float_as_uint(Sp[0]);
            const uint32_t a1 = __float_as_uint(Sp[8 * 68]);
            const uint32_t a2 = __float_as_uint(Sp[4]);
            const uint32_t a3 = __float_as_uint(Sp[8 * 68 + 4]);
            #pragma unroll
            for (int j = 0; j < 2; j++) {
                const float* Vp = &Vrm[(kk + tg) * 40 + (np + j) * 8 + g];
                mma_tf32(oacc[j], a0, a1, a2, a3,
                         __float_as_uint(Vp[0]), __float_as_uint(Vp[160]));
            }
        }
        #pragma unroll
        for (int j = 0; j < 2; j++) {
            const int pb = h * 16 + (np + j) * 4 + tg;
            #pragma unroll
            for (int half = 0; half < 2; half++) {
                const int row = ms + g + half * 8;
                uint32_t lo;
                const uint32_t hi = hsplit2(oacc[j][half * 2], oacc[j][half * 2 + 1], lo);
                g_ath[(size_t)(m0 + row) * 128 + pb] = hi;
                g_atl[(size_t)(m0 + row) * 128 + pb] = lo;
            }
        }
    }
}

// ---------------------------------------------------------------------------
// K4: output projection (2-term fp16) + bias + residual. grid (2, NTOK/128).
// ---------------------------------------------------------------------------
__global__ void __launch_bounds__(256, 2)
outproj_gemm_kernel(const float* __restrict__ x, const float* __restrict__ bo,
                    float* __restrict__ out)
{
    extern __shared__ char smc[];
    const uint32_t sbase = s2u(smc);
    const int tid = threadIdx.x, wid = tid >> 5, lane = tid & 31;
    const int nb = blockIdx.x;           // 0..1
    const int m0 = blockIdx.y * 128;

    float acc[2][8][4] = {};
    gemm_mainloop128_f16_2t(sbase,
                            g_ath + (size_t)m0 * 128, g_atl + (size_t)m0 * 128,
                            g_wh + (size_t)(768 + nb * 128) * 128,
                            acc);

    const int wm = (wid & 3) * 32, wn = (wid >> 2) * 64;
    const int g = lane >> 2, tg = lane & 3;
    const int n0 = nb * 128;
    #pragma unroll
    for (int mi = 0; mi < 2; mi++) {
        #pragma unroll
        for (int half = 0; half < 2; half++) {
            const int r = wm + mi * 16 + g + half * 8;
            int b, pix; tok2pix(m0 + r, b, pix);
            const size_t base = (size_t)b * CH * IMG * IMG + pix;
            #pragma unroll
            for (int nj = 0; nj < 8; nj++) {
                const int c0 = n0 + wn + nj * 8 + 2 * tg;
                const size_t a0 = base + (size_t)c0 * (IMG * IMG);
                const size_t a1 = a0 + (IMG * IMG);
                out[a0] = acc[mi][nj][half * 2 + 0] + bo[c0]     + x[a0];
                out[a1] = acc[mi][nj][half * 2 + 1] + bo[c0 + 1] + x[a1];
            }
        }
    }
}

// ---------------------------------------------------------------------------
extern "C" void kernel_launch(void* const* d_in, const int* in_sizes, int n_in,
                              void* d_out, int out_size)
{
    const float* x    = (const float*)d_in[0];
    const float* gnw  = (const float*)d_in[1];
    const float* gnb  = (const float*)d_in[2];
    const float* Wq   = (const float*)d_in[3];
    const float* Wk   = (const float*)d_in[4];
    const float* Wv   = (const float*)d_in[5];
    const float* Wo   = (const float*)d_in[6];
    const float* bo   = (const float*)d_in[7];
    const float* pos  = (const float*)d_in[8];
    const float* scl  = (const float*)d_in[9];
    float* out = (float*)d_out;

    cudaFuncSetAttribute(qkv_gemm_kernel,     cudaFuncAttributeMaxDynamicSharedMemorySize, GM_SMEM);
    cudaFuncSetAttribute(outproj_gemm_kernel, cudaFuncAttributeMaxDynamicSharedMemorySize, GM_SMEM);
    cudaFuncSetAttribute(attn_kernel,         cudaFuncAttributeMaxDynamicSharedMemorySize, AT_SMEM);

    gn_stats_kernel<<<BATCH * 32, 512>>>(x);
    prep_w_kernel<<<512, 256>>>(Wq, Wk, Wv, Wo);
    prep_x_kernel<<<NTOK / 128, 256>>>(x, gnw, gnb);
    qkv_gemm_kernel<<<dim3(6, NTOK / 128), 256, GM_SMEM>>>(scl);
    attn_kernel<<<NTOK / NT, 256, AT_SMEM>>>(pos);
    outproj_gemm_kernel<<<dim3(2, NTOK / 128), 256, GM_SMEM>>>(x, bo, out);
}